// round 2
// baseline (speedup 1.0000x reference)
#include <cuda_runtime.h>
#include <math.h>

#define D_MODEL 1024
#define FF_DIM  4096
#define BATCH   4
#define SEQ     1024
#define HEADS   16
#define HDIM    64
#define ROWS    (BATCH*SEQ)   // 4096

typedef unsigned long long ull;

// ---------- f32x2 packed-math helpers (sm_103a) ----------
__device__ __forceinline__ ull fma2(ull a, ull b, ull c) {
    ull d;
    asm("fma.rn.f32x2 %0, %1, %2, %3;" : "=l"(d) : "l"(a), "l"(b), "l"(c));
    return d;
}
__device__ __forceinline__ ull mul2(ull a, ull b) {
    ull d;
    asm("mul.rn.f32x2 %0, %1, %2;" : "=l"(d) : "l"(a), "l"(b));
    return d;
}
__device__ __forceinline__ ull dup2(float x) {
    ull d;
    asm("mov.b64 %0, {%1, %1};" : "=l"(d) : "f"(x));
    return d;
}
__device__ __forceinline__ float2 unpk(ull a) {
    float2 r;
    asm("mov.b64 {%0, %1}, %2;" : "=f"(r.x), "=f"(r.y) : "l"(a));
    return r;
}

// ---------------- scratch ----------------
__device__ float g_qkin[ROWS*D_MODEL];
__device__ float g_Q   [ROWS*D_MODEL];
__device__ float g_K   [ROWS*D_MODEL];
__device__ float g_V   [ROWS*D_MODEL];
__device__ float g_attn[ROWS*D_MODEL];
__device__ float g_x1  [ROWS*D_MODEL];
__device__ float g_ff1 [ROWS*FF_DIM];
__device__ float g_h   [ROWS*D_MODEL];

// ---------------- elementwise add ----------------
__global__ __launch_bounds__(256) void add_kernel(const float* __restrict__ a,
                                                  const float* __restrict__ b,
                                                  float* __restrict__ c, int n4)
{
    int i = blockIdx.x * blockDim.x + threadIdx.x;
    if (i < n4) {
        float4 x = ((const float4*)a)[i];
        float4 y = ((const float4*)b)[i];
        x.x += y.x; x.y += y.y; x.z += y.z; x.w += y.w;
        ((float4*)c)[i] = x;
    }
}

// ---------------- SGEMM via packed f32x2 FMA ----------------
// C[M,N] = A[M,K] @ B[K,N] (+epilogue). BM=BN=128, BK=8, 256 threads, 8x8 tile.
// A tile stored DUPLICATED in smem so LDS yields broadcast-packed operands.
// Double-buffered smem, one __syncthreads per k-tile.
// EPI: 0=none, 1=+bias+relu, 2=+bias+residual
template<int EPI>
__global__ __launch_bounds__(256) void sgemm_kernel(const float* __restrict__ A,
                                                    const float* __restrict__ B,
                                                    const float* __restrict__ bias,
                                                    const float* __restrict__ res,
                                                    float* __restrict__ C,
                                                    int M, int N, int K)
{
    __shared__ float As[2][8][256];   // duplicated A: As[k][2r]=As[k][2r+1]=A[r][k]
    __shared__ float Bs[2][8][128];

    const int tid  = threadIdx.x;
    const int brow = blockIdx.y * 128;
    const int bcol = blockIdx.x * 128;
    const int tr   = (tid >> 4) * 8;
    const int tc   = (tid & 15) * 8;
    const int rowA = tid >> 1;
    const int colA = (tid & 1) * 4;
    const int rowB = tid >> 5;
    const int colB = (tid & 31) * 4;

    ull acc[8][4];
    #pragma unroll
    for (int i = 0; i < 8; i++)
        #pragma unroll
        for (int j = 0; j < 4; j++) acc[i][j] = 0ull;

    const float* Ap = A + (size_t)(brow + rowA) * K + colA;
    const float* Bp = B + (size_t)rowB * N + bcol + colB;

    const int T = K >> 3;

    // prologue: tile 0 into buffer 0
    {
        float4 a4 = *(const float4*)(Ap);
        float4 b4 = *(const float4*)(Bp);
        #pragma unroll
        for (int q = 0; q < 4; q++) {
            float v = (&a4.x)[q];
            *(float2*)&As[0][colA + q][2 * rowA] = make_float2(v, v);
        }
        *(float4*)&Bs[0][rowB][colB] = b4;
    }
    __syncthreads();

    for (int t = 0; t < T; ++t) {
        const int cur = t & 1;
        float4 a4n, b4n;
        const bool more = (t + 1 < T);
        if (more) {
            a4n = *(const float4*)(Ap + 8 * (t + 1));
            b4n = *(const float4*)(Bp + (size_t)(8 * (t + 1)) * N);
        }

        #pragma unroll
        for (int k = 0; k < 8; k++) {
            const float* ar = &As[cur][k][0];
            ulonglong2 t0 = *(const ulonglong2*)(ar + 2 * tr);
            ulonglong2 t1 = *(const ulonglong2*)(ar + 2 * tr + 4);
            ulonglong2 t2 = *(const ulonglong2*)(ar + 2 * tr + 8);
            ulonglong2 t3 = *(const ulonglong2*)(ar + 2 * tr + 12);
            ulonglong2 u0 = *(const ulonglong2*)(&Bs[cur][k][tc]);
            ulonglong2 u1 = *(const ulonglong2*)(&Bs[cur][k][tc + 4]);
            ull a8[8] = {t0.x, t0.y, t1.x, t1.y, t2.x, t2.y, t3.x, t3.y};
            ull b4p[4] = {u0.x, u0.y, u1.x, u1.y};
            #pragma unroll
            for (int i = 0; i < 8; i++)
                #pragma unroll
                for (int j = 0; j < 4; j++)
                    acc[i][j] = fma2(a8[i], b4p[j], acc[i][j]);
        }

        if (more) {
            const int nxt = cur ^ 1;
            #pragma unroll
            for (int q = 0; q < 4; q++) {
                float v = (&a4n.x)[q];
                *(float2*)&As[nxt][colA + q][2 * rowA] = make_float2(v, v);
            }
            *(float4*)&Bs[nxt][rowB][colB] = b4n;
            __syncthreads();
        }
    }

    // epilogue
    #pragma unroll
    for (int i = 0; i < 8; i++) {
        size_t row = (size_t)(brow + tr + i);
        float o8[8];
        #pragma unroll
        for (int j = 0; j < 4; j++) {
            float2 v = unpk(acc[i][j]);
            o8[2 * j] = v.x; o8[2 * j + 1] = v.y;
        }
        #pragma unroll
        for (int j = 0; j < 8; j++) {
            int col = bcol + tc + j;
            float v = o8[j];
            if (EPI >= 1) v += bias[col];
            if (EPI == 1) v = fmaxf(v, 0.f);
            if (EPI == 2) v += res[row * (size_t)N + col];
            o8[j] = v;
        }
        *(float4*)&C[row * (size_t)N + bcol + tc]     = make_float4(o8[0], o8[1], o8[2], o8[3]);
        *(float4*)&C[row * (size_t)N + bcol + tc + 4] = make_float4(o8[4], o8[5], o8[6], o8[7]);
    }
}

// ---------------- flash attention, packed f32x2 over contraction dim ----------------
// Grid (SEQ/64, HEADS, BATCH), 256 threads. BR=BC=64, d=64.
// Pairs are taken along k (QK^T) and along c (PV); V is stored transposed in smem.
#define FA_STR  68
#define FA_SMEM (3 * 64 * FA_STR * 4)

__global__ void __launch_bounds__(256, 2) flash_attn_kernel(const float* __restrict__ Qp,
                                                            const float* __restrict__ Kp,
                                                            const float* __restrict__ Vp,
                                                            float* __restrict__ O)
{
    extern __shared__ float sm[];
    float* Qs = sm;                      // 64 x 68   [qrow][k]
    float* Ks = sm + 64 * FA_STR;        // 64 x 68   [krow][k], reused as P[qrow][c]
    float* Vt = sm + 2 * 64 * FA_STR;    // 64 x 68   [d][c]  (transposed)

    const int tid = threadIdx.x;
    const int tx  = tid & 7;    // 0..7
    const int ty  = tid >> 3;   // 0..31
    const int b   = blockIdx.z;
    const int h   = blockIdx.y;
    const int q0  = blockIdx.x * 64;
    const size_t base = ((size_t)b * SEQ) * D_MODEL + (size_t)h * HDIM;

    // Load Q tile, pre-scaled by sqrt(d)=8 (reference quirk)
    for (int v = tid; v < 1024; v += 256) {
        int r = v >> 4, c = (v & 15) << 2;
        float4 t = *(const float4*)(Qp + base + (size_t)(q0 + r) * D_MODEL + c);
        t.x *= 8.f; t.y *= 8.f; t.z *= 8.f; t.w *= 8.f;
        *(float4*)&Qs[r * FA_STR + c] = t;
    }

    float m[2] = {-1e30f, -1e30f};
    float l[2] = {0.f, 0.f};
    ull o2[2][8];
    #pragma unroll
    for (int i = 0; i < 2; i++)
        #pragma unroll
        for (int j = 0; j < 8; j++) o2[i][j] = 0ull;

    for (int kt = 0; kt < SEQ; kt += 64) {
        __syncthreads();  // prior PV reads done
        for (int v = tid; v < 1024; v += 256) {
            int r = v >> 4, c = (v & 15) << 2;
            *(float4*)&Ks[r * FA_STR + c] = *(const float4*)(Kp + base + (size_t)(kt + r) * D_MODEL + c);
            float4 t = *(const float4*)(Vp + base + (size_t)(kt + r) * D_MODEL + c);
            Vt[(c + 0) * FA_STR + r] = t.x;
            Vt[(c + 1) * FA_STR + r] = t.y;
            Vt[(c + 2) * FA_STR + r] = t.z;
            Vt[(c + 3) * FA_STR + r] = t.w;
        }
        __syncthreads();

        // S = (8Q) K^T — packed pairs along k, fold at end
        ull s2[2][8];
        #pragma unroll
        for (int i = 0; i < 2; i++)
            #pragma unroll
            for (int j = 0; j < 8; j++) s2[i][j] = 0ull;

        #pragma unroll 4
        for (int k2 = 0; k2 < 64; k2 += 2) {
            ull qa[2], kb[8];
            qa[0] = *(const ull*)&Qs[ty * FA_STR + k2];
            qa[1] = *(const ull*)&Qs[(ty + 32) * FA_STR + k2];
            #pragma unroll
            for (int j = 0; j < 8; j++)
                kb[j] = *(const ull*)&Ks[(tx + 8 * j) * FA_STR + k2];
            #pragma unroll
            for (int i = 0; i < 2; i++)
                #pragma unroll
                for (int j = 0; j < 8; j++)
                    s2[i][j] = fma2(qa[i], kb[j], s2[i][j]);
        }

        float s[2][8];
        #pragma unroll
        for (int i = 0; i < 2; i++)
            #pragma unroll
            for (int j = 0; j < 8; j++) {
                float2 v = unpk(s2[i][j]);
                s[i][j] = v.x + v.y;
            }

        __syncthreads();  // all Ks reads done; safe to overwrite with P

        // online softmax (8 lanes per row)
        #pragma unroll
        for (int i = 0; i < 2; i++) {
            float mx = s[i][0];
            #pragma unroll
            for (int j = 1; j < 8; j++) mx = fmaxf(mx, s[i][j]);
            #pragma unroll
            for (int off = 1; off < 8; off <<= 1)
                mx = fmaxf(mx, __shfl_xor_sync(0xffffffffu, mx, off));
            float mn   = fmaxf(m[i], mx);
            float corr = __expf(m[i] - mn);
            float rs = 0.f;
            #pragma unroll
            for (int j = 0; j < 8; j++) { s[i][j] = __expf(s[i][j] - mn); rs += s[i][j]; }
            #pragma unroll
            for (int off = 1; off < 8; off <<= 1)
                rs += __shfl_xor_sync(0xffffffffu, rs, off);
            l[i] = l[i] * corr + rs;
            m[i] = mn;
            ull cd = dup2(corr);
            #pragma unroll
            for (int j = 0; j < 8; j++) o2[i][j] = mul2(o2[i][j], cd);
            #pragma unroll
            for (int j = 0; j < 8; j++)
                Ks[(ty + 32 * i) * FA_STR + tx + 8 * j] = s[i][j];
        }
        __syncthreads();

        // O += P V — packed pairs along c
        #pragma unroll 4
        for (int c2 = 0; c2 < 64; c2 += 2) {
            ull pr[2], vb[8];
            pr[0] = *(const ull*)&Ks[ty * FA_STR + c2];
            pr[1] = *(const ull*)&Ks[(ty + 32) * FA_STR + c2];
            #pragma unroll
            for (int j = 0; j < 8; j++)
                vb[j] = *(const ull*)&Vt[(tx + 8 * j) * FA_STR + c2];
            #pragma unroll
            for (int i = 0; i < 2; i++)
                #pragma unroll
                for (int j = 0; j < 8; j++)
                    o2[i][j] = fma2(pr[i], vb[j], o2[i][j]);
        }
    }

    #pragma unroll
    for (int i = 0; i < 2; i++) {
        float inv = 1.f / l[i];
        size_t rowoff = base + (size_t)(q0 + ty + 32 * i) * D_MODEL;
        #pragma unroll
        for (int j = 0; j < 8; j++) {
            float2 v = unpk(o2[i][j]);
            O[rowoff + tx + 8 * j] = (v.x + v.y) * inv;
        }
    }
}

// ---------------- layernorm (optionally fused residual add) ----------------
__global__ __launch_bounds__(256) void ln_kernel(const float* __restrict__ A,
                                                 const float* __restrict__ Add,
                                                 const float* __restrict__ g,
                                                 const float* __restrict__ bb,
                                                 float* __restrict__ out,
                                                 int useAdd)
{
    __shared__ float red[8];
    const int row = blockIdx.x;
    const size_t off = (size_t)row * D_MODEL;
    const int tid = threadIdx.x;

    float x[4]; float s = 0.f;
    #pragma unroll
    for (int i = 0; i < 4; i++) {
        int c = tid + 256 * i;
        float v = A[off + c];
        if (useAdd) v += Add[off + c];
        x[i] = v; s += v;
    }
    #pragma unroll
    for (int o = 16; o > 0; o >>= 1) s += __shfl_xor_sync(0xffffffffu, s, o);
    if ((tid & 31) == 0) red[tid >> 5] = s;
    __syncthreads();
    float tot = 0.f;
    #pragma unroll
    for (int i = 0; i < 8; i++) tot += red[i];
    const float mean = tot * (1.0f / 1024.0f);

    float vs = 0.f;
    #pragma unroll
    for (int i = 0; i < 4; i++) { float d = x[i] - mean; vs += d * d; }
    #pragma unroll
    for (int o = 16; o > 0; o >>= 1) vs += __shfl_xor_sync(0xffffffffu, vs, o);
    __syncthreads();
    if ((tid & 31) == 0) red[tid >> 5] = vs;
    __syncthreads();
    float vt = 0.f;
    #pragma unroll
    for (int i = 0; i < 8; i++) vt += red[i];
    const float inv = rsqrtf(vt * (1.0f / 1024.0f) + 1e-5f);

    #pragma unroll
    for (int i = 0; i < 4; i++) {
        int c = tid + 256 * i;
        out[off + c] = (x[i] - mean) * inv * g[c] + bb[c];
    }
}

// ---------------- launch ----------------
extern "C" void kernel_launch(void* const* d_in, const int* in_sizes, int n_in,
                              void* d_out, int out_size)
{
    const float* input = (const float*)d_in[0];
    const float* pos   = (const float*)d_in[1];
    const float* Wq    = (const float*)d_in[2];
    const float* Wk    = (const float*)d_in[3];
    const float* Wv    = (const float*)d_in[4];
    const float* W1    = (const float*)d_in[5];
    const float* b1    = (const float*)d_in[6];
    const float* W2    = (const float*)d_in[7];
    const float* b2    = (const float*)d_in[8];
    const float* ln1g  = (const float*)d_in[9];
    const float* ln1b  = (const float*)d_in[10];
    const float* ln2g  = (const float*)d_in[11];
    const float* ln2b  = (const float*)d_in[12];
    float* out = (float*)d_out;

    float *qkin, *Q, *K, *V, *attn, *x1, *ff1, *h;
    cudaGetSymbolAddress((void**)&qkin, g_qkin);
    cudaGetSymbolAddress((void**)&Q,    g_Q);
    cudaGetSymbolAddress((void**)&K,    g_K);
    cudaGetSymbolAddress((void**)&V,    g_V);
    cudaGetSymbolAddress((void**)&attn, g_attn);
    cudaGetSymbolAddress((void**)&x1,   g_x1);
    cudaGetSymbolAddress((void**)&ff1,  g_ff1);
    cudaGetSymbolAddress((void**)&h,    g_h);

    cudaFuncSetAttribute(flash_attn_kernel,
                         cudaFuncAttributeMaxDynamicSharedMemorySize, FA_SMEM);

    // 1) qk_in = input + pos
    {
        int n4 = ROWS * D_MODEL / 4;
        add_kernel<<<(n4 + 255) / 256, 256>>>(input, pos, qkin, n4);
    }

    // 2) Q/K/V projections
    {
        dim3 g1(D_MODEL / 128, ROWS / 128);
        sgemm_kernel<0><<<g1, 256>>>(qkin,  Wq, nullptr, nullptr, Q, ROWS, D_MODEL, D_MODEL);
        sgemm_kernel<0><<<g1, 256>>>(qkin,  Wk, nullptr, nullptr, K, ROWS, D_MODEL, D_MODEL);
        sgemm_kernel<0><<<g1, 256>>>(input, Wv, nullptr, nullptr, V, ROWS, D_MODEL, D_MODEL);
    }

    // 3) attention
    {
        dim3 ga(SEQ / 64, HEADS, BATCH);
        flash_attn_kernel<<<ga, 256, FA_SMEM>>>(Q, K, V, attn);
    }

    // 4) x1 = LN(input + attn)
    ln_kernel<<<ROWS, 256>>>(input, attn, ln1g, ln1b, x1, 1);

    // 5) ff1 = relu(x1 @ W1 + b1)
    {
        dim3 g2(FF_DIM / 128, ROWS / 128);
        sgemm_kernel<1><<<g2, 256>>>(x1, W1, b1, nullptr, ff1, ROWS, FF_DIM, D_MODEL);
    }

    // 6) h = ff1 @ W2 + b2 + x1
    {
        dim3 g3(D_MODEL / 128, ROWS / 128);
        sgemm_kernel<2><<<g3, 256>>>(ff1, W2, b2, x1, h, ROWS, D_MODEL, FF_DIM);
    }

    // 7) out = LN(h)
    ln_kernel<<<ROWS, 256>>>(h, h, ln2g, ln2b, out, 0);
}

// round 4
// speedup vs baseline: 1.5701x; 1.5701x over previous
#include <cuda_runtime.h>
#include <math.h>
#include <stdint.h>

#define D_MODEL 1024
#define FF_DIM  4096
#define BATCH   4
#define SEQ     1024
#define HEADS   16
#define HDIM    64
#define ROWS    (BATCH*SEQ)   // 4096

// ================= scratch =================
__device__ float g_qkin [ROWS*D_MODEL];
__device__ float g_QKV  [ROWS*3*D_MODEL];   // [4096, 3072]: Q | K | V
__device__ float g_attn [ROWS*D_MODEL];
__device__ float g_x1   [ROWS*D_MODEL];
__device__ float g_ff1  [ROWS*FF_DIM];
__device__ float g_h    [ROWS*D_MODEL];
__device__ float g_WqkvT[3*D_MODEL*D_MODEL];  // [3072,1024]
__device__ float g_W1T  [FF_DIM*D_MODEL];     // [4096,1024]
__device__ float g_W2T  [D_MODEL*FF_DIM];     // [1024,4096]

// ================= helpers =================
__device__ __forceinline__ uint32_t smem_u32(const void* p) {
    uint32_t a;
    asm("{ .reg .u64 t; cvta.to.shared.u64 t, %1; cvt.u32.u64 %0, t; }" : "=r"(a) : "l"(p));
    return a;
}
__device__ __forceinline__ void split2(float x, uint32_t& hi, uint32_t& lo) {
    uint32_t h;
    asm("cvt.rna.tf32.f32 %0, %1;" : "=r"(h) : "f"(x));
    float l = x - __uint_as_float(h);
    asm("cvt.rna.tf32.f32 %0, %1;" : "=r"(lo) : "f"(l));
    hi = h;
}
__device__ __forceinline__ void ldsm_x4(uint32_t* r, uint32_t addr) {
    asm volatile("ldmatrix.sync.aligned.m8n8.x4.shared.b16 {%0,%1,%2,%3}, [%4];"
                 : "=r"(r[0]), "=r"(r[1]), "=r"(r[2]), "=r"(r[3]) : "r"(addr));
}
__device__ __forceinline__ void ldsm_x2(uint32_t* r, uint32_t addr) {
    asm volatile("ldmatrix.sync.aligned.m8n8.x2.shared.b16 {%0,%1}, [%2];"
                 : "=r"(r[0]), "=r"(r[1]) : "r"(addr));
}
__device__ __forceinline__ void mma_tf32(float* d, const uint32_t* a, const uint32_t* b) {
    asm volatile("mma.sync.aligned.m16n8k8.row.col.f32.tf32.tf32.f32 "
                 "{%0,%1,%2,%3}, {%4,%5,%6,%7}, {%8,%9}, {%0,%1,%2,%3};"
                 : "+f"(d[0]), "+f"(d[1]), "+f"(d[2]), "+f"(d[3])
                 : "r"(a[0]), "r"(a[1]), "r"(a[2]), "r"(a[3]), "r"(b[0]), "r"(b[1]));
}

// ================= weight transpose =================
__global__ __launch_bounds__(256) void transpose_kernel(const float* __restrict__ in,
                                                        float* __restrict__ out,
                                                        int R, int C)
{
    __shared__ float t[32][33];
    const int cb = blockIdx.x * 32, rb = blockIdx.y * 32;
    const int tx = threadIdx.x & 31, ty = threadIdx.x >> 5;
    #pragma unroll
    for (int i = 0; i < 4; i++)
        t[ty + 8 * i][tx] = in[(size_t)(rb + ty + 8 * i) * C + cb + tx];
    __syncthreads();
    #pragma unroll
    for (int i = 0; i < 4; i++)
        out[(size_t)(cb + ty + 8 * i) * R + rb + tx] = t[tx][ty + 8 * i];
}

// ================= elementwise add =================
__global__ __launch_bounds__(256) void add_kernel(const float* __restrict__ a,
                                                  const float* __restrict__ b,
                                                  float* __restrict__ c, int n4)
{
    int i = blockIdx.x * blockDim.x + threadIdx.x;
    if (i < n4) {
        float4 x = ((const float4*)a)[i];
        float4 y = ((const float4*)b)[i];
        x.x += y.x; x.y += y.y; x.z += y.z; x.w += y.w;
        ((float4*)c)[i] = x;
    }
}

// ================= mma.sync tf32 GEMM (3xTF32) =================
// C[4096, ldc] tile [m0:+128, n0:+64] = A[4096,K] @ Bt[ldc,K]^T
// CTA 128x64x16, 256 thr, 8 warps (2m x 4n), warp tile 64x16.
// smem per buffer (u32): Ahi[128*20] Alo[128*20] Bhi[64*20] Blo[64*20] = 7680 u32
#define PAD      20
#define ABUF_U32 (128 * PAD)          // 2560
#define BBUF_U32 (64 * PAD)           // 1280
#define BUF_U32  (2 * ABUF_U32 + 2 * BBUF_U32)  // 7680
#define MG_SMEM  (2 * BUF_U32 * 4)    // 61440 bytes

template<int EPI, bool QKVSEL>
__global__ void __launch_bounds__(256, 2)
mma_gemm_kernel(const float* __restrict__ A0, const float* __restrict__ A1,
                const float* __restrict__ Bt,
                const float* __restrict__ bias, const float* __restrict__ res,
                float* __restrict__ C, int K, int ldc)
{
    extern __shared__ uint32_t dsm[];
    const int tid  = threadIdx.x;
    const int wid  = tid >> 5;
    const int lane = tid & 31;
    const int m0   = blockIdx.y * 128;
    const int n0   = blockIdx.x * 64;
    const int wm   = wid & 1;       // 0..1
    const int wn   = wid >> 1;      // 0..3
    const float* A = QKVSEL ? ((n0 < 2 * D_MODEL) ? A0 : A1) : A0;

    const uint32_t sbase = smem_u32(dsm);

    float acc[4][2][4];
    #pragma unroll
    for (int i = 0; i < 4; i++)
        #pragma unroll
        for (int j = 0; j < 2; j++)
            #pragma unroll
            for (int q = 0; q < 4; q++) acc[i][j][q] = 0.f;

    // staging indices
    const int arow = tid >> 1;                    // A: idx = tid + 256*i -> row idx>>2
    const int T = K >> 4;

    // prefetch regs
    float4 pa[2], pb;

    auto LOAD = [&](int kc) {
        #pragma unroll
        for (int i = 0; i < 2; i++) {
            int idx = tid + 256 * i;
            int r = idx >> 2, c4 = idx & 3;
            pa[i] = *(const float4*)(A + (size_t)(m0 + r) * K + kc + c4 * 4);
        }
        {
            int r = tid >> 2, c4 = tid & 3;
            pb = *(const float4*)(Bt + (size_t)(n0 + r) * K + kc + c4 * 4);
        }
    };
    auto STORE = [&](int p) {
        uint32_t* Ah = dsm + p * BUF_U32;
        uint32_t* Al = Ah + ABUF_U32;
        uint32_t* Bh = Al + ABUF_U32;
        uint32_t* Bl = Bh + BBUF_U32;
        #pragma unroll
        for (int i = 0; i < 2; i++) {
            int idx = tid + 256 * i;
            int r = idx >> 2, c4 = idx & 3;
            uint4 hv, lv;
            split2(pa[i].x, hv.x, lv.x); split2(pa[i].y, hv.y, lv.y);
            split2(pa[i].z, hv.z, lv.z); split2(pa[i].w, hv.w, lv.w);
            *(uint4*)(Ah + r * PAD + c4 * 4) = hv;
            *(uint4*)(Al + r * PAD + c4 * 4) = lv;
        }
        {
            int r = tid >> 2, c4 = tid & 3;
            uint4 hv, lv;
            split2(pb.x, hv.x, lv.x); split2(pb.y, hv.y, lv.y);
            split2(pb.z, hv.z, lv.z); split2(pb.w, hv.w, lv.w);
            *(uint4*)(Bh + r * PAD + c4 * 4) = hv;
            *(uint4*)(Bl + r * PAD + c4 * 4) = lv;
        }
    };

    LOAD(0);
    STORE(0);
    __syncthreads();

    // per-lane ldmatrix address components
    const int a_r  = wm * 64 + (lane & 15);         // + mt*16
    const int a_cs = ((lane >> 4) & 1) * 4;         // + ks*8
    const int b_r  = wn * 16 + (lane & 7);          // + nt*8
    const int b_cs = ((lane >> 3) & 1) * 4;         // + ks*8

    for (int t = 0; t < T; t++) {
        const int p = t & 1;
        const bool more = (t + 1 < T);
        if (more) LOAD((t + 1) << 4);

        const uint32_t aHi = sbase + (p * BUF_U32) * 4;
        const uint32_t aLo = aHi + ABUF_U32 * 4;
        const uint32_t bHi = aLo + ABUF_U32 * 4;
        const uint32_t bLo = bHi + BBUF_U32 * 4;

        #pragma unroll
        for (int ks = 0; ks < 2; ks++) {
            uint32_t ah[4][4], al[4][4];
            #pragma unroll
            for (int mt = 0; mt < 4; mt++) {
                uint32_t off = ((a_r + mt * 16) * PAD + ks * 8 + a_cs) * 4;
                ldsm_x4(ah[mt], aHi + off);
                ldsm_x4(al[mt], aLo + off);
            }
            uint32_t bh[2][2], bl[2][2];
            #pragma unroll
            for (int nt = 0; nt < 2; nt++) {
                uint32_t off = ((b_r + nt * 8) * PAD + ks * 8 + b_cs) * 4;
                ldsm_x2(bh[nt], bHi + off);
                ldsm_x2(bl[nt], bLo + off);
            }
            #pragma unroll
            for (int mt = 0; mt < 4; mt++)
                #pragma unroll
                for (int nt = 0; nt < 2; nt++) {
                    mma_tf32(acc[mt][nt], ah[mt], bh[nt]);
                    mma_tf32(acc[mt][nt], ah[mt], bl[nt]);
                    mma_tf32(acc[mt][nt], al[mt], bh[nt]);
                }
        }

        if (more) STORE(p ^ 1);
        __syncthreads();
    }

    // ---- epilogue ----
    const int g  = lane >> 2;
    const int tg = lane & 3;
    #pragma unroll
    for (int mt = 0; mt < 4; mt++) {
        #pragma unroll
        for (int nt = 0; nt < 2; nt++) {
            int row = m0 + wm * 64 + mt * 16 + g;
            int col = n0 + wn * 16 + nt * 8 + 2 * tg;
            #pragma unroll
            for (int hh = 0; hh < 2; hh++) {   // row, row+8
                int r = row + hh * 8;
                float2 v;
                v.x = acc[mt][nt][2 * hh + 0];
                v.y = acc[mt][nt][2 * hh + 1];
                if (EPI >= 1) { v.x += bias[col]; v.y += bias[col + 1]; }
                if (EPI == 1) { v.x = fmaxf(v.x, 0.f); v.y = fmaxf(v.y, 0.f); }
                if (EPI == 2) {
                    const float2 rr = *(const float2*)(res + (size_t)r * ldc + col);
                    v.x += rr.x; v.y += rr.y;
                }
                *(float2*)(C + (size_t)r * ldc + col) = v;
            }
        }
    }
}

// ================= flash attention (fp32, R1-proven, fused-QKV layout) =================
#define FA_STR  68
#define FA_SMEM (3 * 64 * FA_STR * 4)
#define QKV_LD  (3 * D_MODEL)

__global__ __launch_bounds__(128) void flash_attn_kernel(const float* __restrict__ QKV,
                                                         float* __restrict__ O)
{
    extern __shared__ float sm[];
    float* Qs = sm;                      // 64 x 68
    float* Ks = sm + 64 * FA_STR;        // 64 x 68 (reused as P)
    float* Vs = sm + 2 * 64 * FA_STR;    // 64 x 68

    const int tid = threadIdx.x;
    const int ty  = tid >> 3;
    const int tx  = tid & 7;
    const int b   = blockIdx.z;
    const int h   = blockIdx.y;
    const int q0  = blockIdx.x * 64;
    const size_t rowb = (size_t)b * SEQ;
    const size_t qoff = rowb * QKV_LD + (size_t)h * HDIM;

    for (int v = tid; v < 1024; v += 128) {
        int r = v >> 4, c = (v & 15) << 2;
        float4 t = *(const float4*)(QKV + qoff + (size_t)(q0 + r) * QKV_LD + c);
        t.x *= 8.f; t.y *= 8.f; t.z *= 8.f; t.w *= 8.f;
        *(float4*)&Qs[r * FA_STR + c] = t;
    }

    float m[4], l[4], o[4][8];
    #pragma unroll
    for (int i = 0; i < 4; i++) {
        m[i] = -1e30f; l[i] = 0.f;
        #pragma unroll
        for (int j = 0; j < 8; j++) o[i][j] = 0.f;
    }

    for (int kt = 0; kt < SEQ; kt += 64) {
        __syncthreads();
        for (int v = tid; v < 1024; v += 128) {
            int r = v >> 4, c = (v & 15) << 2;
            *(float4*)&Ks[r * FA_STR + c] =
                *(const float4*)(QKV + qoff + D_MODEL + (size_t)(kt + r) * QKV_LD + c);
            *(float4*)&Vs[r * FA_STR + c] =
                *(const float4*)(QKV + qoff + 2 * D_MODEL + (size_t)(kt + r) * QKV_LD + c);
        }
        __syncthreads();

        float s[4][8];
        #pragma unroll
        for (int i = 0; i < 4; i++)
            #pragma unroll
            for (int j = 0; j < 8; j++) s[i][j] = 0.f;

        #pragma unroll 4
        for (int k = 0; k < 64; k++) {
            float qa[4], kb[8];
            #pragma unroll
            for (int i = 0; i < 4; i++) qa[i] = Qs[(ty + 16 * i) * FA_STR + k];
            #pragma unroll
            for (int j = 0; j < 8; j++) kb[j] = Ks[(tx + 8 * j) * FA_STR + k];
            #pragma unroll
            for (int i = 0; i < 4; i++)
                #pragma unroll
                for (int j = 0; j < 8; j++) s[i][j] = fmaf(qa[i], kb[j], s[i][j]);
        }

        __syncthreads();

        #pragma unroll
        for (int i = 0; i < 4; i++) {
            float mx = s[i][0];
            #pragma unroll
            for (int j = 1; j < 8; j++) mx = fmaxf(mx, s[i][j]);
            #pragma unroll
            for (int off = 1; off < 8; off <<= 1)
                mx = fmaxf(mx, __shfl_xor_sync(0xffffffffu, mx, off));
            float mn   = fmaxf(m[i], mx);
            float corr = __expf(m[i] - mn);
            float rs = 0.f;
            #pragma unroll
            for (int j = 0; j < 8; j++) { s[i][j] = __expf(s[i][j] - mn); rs += s[i][j]; }
            #pragma unroll
            for (int off = 1; off < 8; off <<= 1)
                rs += __shfl_xor_sync(0xffffffffu, rs, off);
            l[i] = l[i] * corr + rs;
            m[i] = mn;
            #pragma unroll
            for (int j = 0; j < 8; j++) o[i][j] *= corr;
            #pragma unroll
            for (int j = 0; j < 8; j++) Ks[(ty + 16 * i) * FA_STR + tx + 8 * j] = s[i][j];
        }
        __syncthreads();

        #pragma unroll 4
        for (int c = 0; c < 64; c++) {
            float pr[4], vb[8];
            #pragma unroll
            for (int i = 0; i < 4; i++) pr[i] = Ks[(ty + 16 * i) * FA_STR + c];
            #pragma unroll
            for (int j = 0; j < 8; j++) vb[j] = Vs[c * FA_STR + tx + 8 * j];
            #pragma unroll
            for (int i = 0; i < 4; i++)
                #pragma unroll
                for (int j = 0; j < 8; j++) o[i][j] = fmaf(pr[i], vb[j], o[i][j]);
        }
    }

    const size_t obase = rowb * D_MODEL + (size_t)h * HDIM;
    #pragma unroll
    for (int i = 0; i < 4; i++) {
        float inv = 1.f / l[i];
        size_t rowoff = obase + (size_t)(q0 + ty + 16 * i) * D_MODEL;
        #pragma unroll
        for (int j = 0; j < 8; j++) O[rowoff + tx + 8 * j] = o[i][j] * inv;
    }
}

// ================= layernorm =================
__global__ __launch_bounds__(256) void ln_kernel(const float* __restrict__ A,
                                                 const float* __restrict__ Add,
                                                 const float* __restrict__ g,
                                                 const float* __restrict__ bb,
                                                 float* __restrict__ out,
                                                 int useAdd)
{
    __shared__ float red[8];
    const int row = blockIdx.x;
    const size_t off = (size_t)row * D_MODEL;
    const int tid = threadIdx.x;

    float x[4]; float s = 0.f;
    #pragma unroll
    for (int i = 0; i < 4; i++) {
        int c = tid + 256 * i;
        float v = A[off + c];
        if (useAdd) v += Add[off + c];
        x[i] = v; s += v;
    }
    #pragma unroll
    for (int o = 16; o > 0; o >>= 1) s += __shfl_xor_sync(0xffffffffu, s, o);
    if ((tid & 31) == 0) red[tid >> 5] = s;
    __syncthreads();
    float tot = 0.f;
    #pragma unroll
    for (int i = 0; i < 8; i++) tot += red[i];
    const float mean = tot * (1.0f / 1024.0f);

    float vs = 0.f;
    #pragma unroll
    for (int i = 0; i < 4; i++) { float d = x[i] - mean; vs += d * d; }
    #pragma unroll
    for (int o = 16; o > 0; o >>= 1) vs += __shfl_xor_sync(0xffffffffu, vs, o);
    __syncthreads();
    if ((tid & 31) == 0) red[tid >> 5] = vs;
    __syncthreads();
    float vt = 0.f;
    #pragma unroll
    for (int i = 0; i < 8; i++) vt += red[i];
    const float inv = rsqrtf(vt * (1.0f / 1024.0f) + 1e-5f);

    #pragma unroll
    for (int i = 0; i < 4; i++) {
        int c = tid + 256 * i;
        out[off + c] = (x[i] - mean) * inv * g[c] + bb[c];
    }
}

// ================= launch =================
extern "C" void kernel_launch(void* const* d_in, const int* in_sizes, int n_in,
                              void* d_out, int out_size)
{
    const float* input = (const float*)d_in[0];
    const float* pos   = (const float*)d_in[1];
    const float* Wq    = (const float*)d_in[2];
    const float* Wk    = (const float*)d_in[3];
    const float* Wv    = (const float*)d_in[4];
    const float* W1    = (const float*)d_in[5];
    const float* b1    = (const float*)d_in[6];
    const float* W2    = (const float*)d_in[7];
    const float* b2    = (const float*)d_in[8];
    const float* ln1g  = (const float*)d_in[9];
    const float* ln1b  = (const float*)d_in[10];
    const float* ln2g  = (const float*)d_in[11];
    const float* ln2b  = (const float*)d_in[12];
    float* out = (float*)d_out;

    float *qkin, *QKV, *attn, *x1, *ff1, *h, *WqkvT, *W1T, *W2T;
    cudaGetSymbolAddress((void**)&qkin,  g_qkin);
    cudaGetSymbolAddress((void**)&QKV,   g_QKV);
    cudaGetSymbolAddress((void**)&attn,  g_attn);
    cudaGetSymbolAddress((void**)&x1,    g_x1);
    cudaGetSymbolAddress((void**)&ff1,   g_ff1);
    cudaGetSymbolAddress((void**)&h,     g_h);
    cudaGetSymbolAddress((void**)&WqkvT, g_WqkvT);
    cudaGetSymbolAddress((void**)&W1T,   g_W1T);
    cudaGetSymbolAddress((void**)&W2T,   g_W2T);

    cudaFuncSetAttribute(flash_attn_kernel,
                         cudaFuncAttributeMaxDynamicSharedMemorySize, FA_SMEM);
    cudaFuncSetAttribute(mma_gemm_kernel<0, true>,
                         cudaFuncAttributeMaxDynamicSharedMemorySize, MG_SMEM);
    cudaFuncSetAttribute(mma_gemm_kernel<1, false>,
                         cudaFuncAttributeMaxDynamicSharedMemorySize, MG_SMEM);
    cudaFuncSetAttribute(mma_gemm_kernel<2, false>,
                         cudaFuncAttributeMaxDynamicSharedMemorySize, MG_SMEM);

    // 0) weight transposes (B must be [N,K] K-major)
    transpose_kernel<<<dim3(32, 32),  256>>>(Wq, WqkvT,                   1024, 1024);
    transpose_kernel<<<dim3(32, 32),  256>>>(Wk, WqkvT + 1024 * 1024,     1024, 1024);
    transpose_kernel<<<dim3(32, 32),  256>>>(Wv, WqkvT + 2 * 1024 * 1024, 1024, 1024);
    transpose_kernel<<<dim3(128, 32), 256>>>(W1, W1T, 1024, 4096);
    transpose_kernel<<<dim3(32, 128), 256>>>(W2, W2T, 4096, 1024);

    // 1) qk_in = input + pos
    {
        int n4 = ROWS * D_MODEL / 4;
        add_kernel<<<(n4 + 255) / 256, 256>>>(input, pos, qkin, n4);
    }

    // 2) fused QKV projection
    mma_gemm_kernel<0, true><<<dim3(48, 32), 256, MG_SMEM>>>(
        qkin, input, WqkvT, nullptr, nullptr, QKV, 1024, 3 * D_MODEL);

    // 3) attention
    {
        dim3 ga(SEQ / 64, HEADS, BATCH);
        flash_attn_kernel<<<ga, 128, FA_SMEM>>>(QKV, attn);
    }

    // 4) x1 = LN(input + attn)
    ln_kernel<<<ROWS, 256>>>(input, attn, ln1g, ln1b, x1, 1);

    // 5) ff1 = relu(x1 @ W1 + b1)
    mma_gemm_kernel<1, false><<<dim3(64, 32), 256, MG_SMEM>>>(
        x1, nullptr, W1T, b1, nullptr, ff1, 1024, FF_DIM);

    // 6) h = ff1 @ W2 + b2 + x1
    mma_gemm_kernel<2, false><<<dim3(16, 32), 256, MG_SMEM>>>(
        ff1, nullptr, W2T, b2, x1, h, 4096, D_MODEL);

    // 7) out = LN(h)
    ln_kernel<<<ROWS, 256>>>(h, h, ln2g, ln2b, out, 0);
}

// round 5
// speedup vs baseline: 1.6192x; 1.0313x over previous
#include <cuda_runtime.h>
#include <math.h>
#include <stdint.h>

#define D_MODEL 1024
#define FF_DIM  4096
#define BATCH   4
#define SEQ     1024
#define HEADS   16
#define HDIM    64
#define ROWS    (BATCH*SEQ)   // 4096

// ================= scratch =================
__device__ float g_qkin [ROWS*D_MODEL];
__device__ float g_QKV  [ROWS*3*D_MODEL];   // [4096, 3072]: Q | K | V
__device__ float g_attn [ROWS*D_MODEL];
__device__ float g_x1   [ROWS*D_MODEL];
__device__ float g_ff1  [ROWS*FF_DIM];
__device__ float g_h    [ROWS*D_MODEL];
__device__ float g_WqkvT[3*D_MODEL*D_MODEL];  // [3072,1024]
__device__ float g_W1T  [FF_DIM*D_MODEL];     // [4096,1024]
__device__ float g_W2T  [D_MODEL*FF_DIM];     // [1024,4096]

// ================= helpers =================
__device__ __forceinline__ uint32_t smem_u32(const void* p) {
    uint32_t a;
    asm("{ .reg .u64 t; cvta.to.shared.u64 t, %1; cvt.u32.u64 %0, t; }" : "=r"(a) : "l"(p));
    return a;
}
__device__ __forceinline__ void split2(float x, uint32_t& hi, uint32_t& lo) {
    uint32_t h;
    asm("cvt.rna.tf32.f32 %0, %1;" : "=r"(h) : "f"(x));
    float l = x - __uint_as_float(h);
    asm("cvt.rna.tf32.f32 %0, %1;" : "=r"(lo) : "f"(l));
    hi = h;
}
__device__ __forceinline__ void splitu(uint32_t raw, uint32_t& hi, uint32_t& lo) {
    split2(__uint_as_float(raw), hi, lo);
}
__device__ __forceinline__ void ldsm_x4(uint32_t* r, uint32_t addr) {
    asm volatile("ldmatrix.sync.aligned.m8n8.x4.shared.b16 {%0,%1,%2,%3}, [%4];"
                 : "=r"(r[0]), "=r"(r[1]), "=r"(r[2]), "=r"(r[3]) : "r"(addr));
}
__device__ __forceinline__ void ldsm_x2(uint32_t* r, uint32_t addr) {
    asm volatile("ldmatrix.sync.aligned.m8n8.x2.shared.b16 {%0,%1}, [%2];"
                 : "=r"(r[0]), "=r"(r[1]) : "r"(addr));
}
__device__ __forceinline__ void mma_tf32(float* d, const uint32_t* a, const uint32_t* b) {
    asm volatile("mma.sync.aligned.m16n8k8.row.col.f32.tf32.tf32.f32 "
                 "{%0,%1,%2,%3}, {%4,%5,%6,%7}, {%8,%9}, {%0,%1,%2,%3};"
                 : "+f"(d[0]), "+f"(d[1]), "+f"(d[2]), "+f"(d[3])
                 : "r"(a[0]), "r"(a[1]), "r"(a[2]), "r"(a[3]), "r"(b[0]), "r"(b[1]));
}
#define CP_ASYNC16(dst, src) \
    asm volatile("cp.async.cg.shared.global [%0], [%1], 16;" :: "r"(dst), "l"(src))
#define CP_COMMIT() asm volatile("cp.async.commit_group;" ::: "memory")
#define CP_WAIT0()  asm volatile("cp.async.wait_group 0;" ::: "memory")

// ================= weight transpose =================
__global__ __launch_bounds__(256) void transpose_kernel(const float* __restrict__ in,
                                                        float* __restrict__ out,
                                                        int R, int C)
{
    __shared__ float t[32][33];
    const int cb = blockIdx.x * 32, rb = blockIdx.y * 32;
    const int tx = threadIdx.x & 31, ty = threadIdx.x >> 5;
    #pragma unroll
    for (int i = 0; i < 4; i++)
        t[ty + 8 * i][tx] = in[(size_t)(rb + ty + 8 * i) * C + cb + tx];
    __syncthreads();
    #pragma unroll
    for (int i = 0; i < 4; i++)
        out[(size_t)(cb + ty + 8 * i) * R + rb + tx] = t[tx][ty + 8 * i];
}

// ================= elementwise add =================
__global__ __launch_bounds__(256) void add_kernel(const float* __restrict__ a,
                                                  const float* __restrict__ b,
                                                  float* __restrict__ c, int n4)
{
    int i = blockIdx.x * blockDim.x + threadIdx.x;
    if (i < n4) {
        float4 x = ((const float4*)a)[i];
        float4 y = ((const float4*)b)[i];
        x.x += y.x; x.y += y.y; x.z += y.z; x.w += y.w;
        ((float4*)c)[i] = x;
    }
}

// ================= mma.sync tf32 GEMM (3xTF32, register-side split) =================
// C[4096, ldc] tile [m0:+128, n0:+128] = A[4096,K] @ Bt[ldc,K]^T
// CTA 128x128x32, 256 thr, 8 warps (2m x 4n), warp tile 64x32.
// smem: fp32 tiles only. PAD=36 u32 per row (144 B, LDSM conflict-free).
#define PAD       36
#define ROWB      (PAD * 4)               // 144 bytes per row
#define ABUF_B    (128 * ROWB)            // 18432 B
#define BBUF_B    (128 * ROWB)            // 18432 B
#define BUF_B     (ABUF_B + BBUF_B)       // 36864 B
#define MG_SMEM   (2 * BUF_B)             // 73728 B
#define KC        32

template<int EPI, bool QKVSEL>
__global__ void __launch_bounds__(256, 1)
mma_gemm_kernel(const float* __restrict__ A0, const float* __restrict__ A1,
                const float* __restrict__ Bt,
                const float* __restrict__ bias, const float* __restrict__ res,
                float* __restrict__ C, int K, int ldc)
{
    extern __shared__ uint32_t dsm[];
    const int tid  = threadIdx.x;
    const int wid  = tid >> 5;
    const int lane = tid & 31;
    const int m0   = blockIdx.y * 128;
    const int n0   = blockIdx.x * 128;
    const int wm   = wid & 1;       // 0..1
    const int wn   = wid >> 1;      // 0..3
    const float* A = QKVSEL ? ((n0 < 2 * D_MODEL) ? A0 : A1) : A0;

    const uint32_t sbase = smem_u32(dsm);

    float acc[4][4][4];
    #pragma unroll
    for (int i = 0; i < 4; i++)
        #pragma unroll
        for (int j = 0; j < 4; j++)
            #pragma unroll
            for (int q = 0; q < 4; q++) acc[i][j][q] = 0.f;

    const int T = K / KC;

    // staging: 1024 chunks of 16B per tile (A and B each), 4 per thread
    const int s_r  = tid >> 1;          // chunk row when paired: idx>>3
    auto STAGE = [&](int p, int kc) {
        const uint32_t Ab = sbase + p * BUF_B;
        const uint32_t Bb = Ab + ABUF_B;
        #pragma unroll
        for (int i = 0; i < 4; i++) {
            int idx = tid + 256 * i;
            int r = idx >> 3, ch = idx & 7;
            CP_ASYNC16(Ab + r * ROWB + ch * 16, A  + (size_t)(m0 + r) * K + kc + ch * 4);
            CP_ASYNC16(Bb + r * ROWB + ch * 16, Bt + (size_t)(n0 + r) * K + kc + ch * 4);
        }
        CP_COMMIT();
    };

    STAGE(0, 0);
    CP_WAIT0();
    __syncthreads();

    // ldmatrix lane address components (validated in R4)
    const int a_r  = wm * 64 + (lane & 15);          // + mt*16
    const int a_c4 = ((lane >> 4) & 1) * 4;          // + ks*8  (fp32 col)
    const int b_r  = wn * 32 + (lane & 7);           // + nt*8
    const int b_c4 = ((lane >> 3) & 1) * 4;          // + ks*8

    for (int t = 0; t < T; t++) {
        const int p = t & 1;
        const bool more = (t + 1 < T);
        if (more) STAGE(p ^ 1, (t + 1) * KC);

        const uint32_t Ab = sbase + p * BUF_B;
        const uint32_t Bb = Ab + ABUF_B;

        #pragma unroll
        for (int ks = 0; ks < 4; ks++) {
            uint32_t raw[4], ah[4][4], al[4][4], bh[4][2], bl[4][2];
            #pragma unroll
            for (int mt = 0; mt < 4; mt++) {
                ldsm_x4(raw, Ab + (a_r + mt * 16) * ROWB + (ks * 8 + a_c4) * 4);
                #pragma unroll
                for (int q = 0; q < 4; q++) splitu(raw[q], ah[mt][q], al[mt][q]);
            }
            #pragma unroll
            for (int nt = 0; nt < 4; nt++) {
                ldsm_x2(raw, Bb + (b_r + nt * 8) * ROWB + (ks * 8 + b_c4) * 4);
                #pragma unroll
                for (int q = 0; q < 2; q++) splitu(raw[q], bh[nt][q], bl[nt][q]);
            }
            #pragma unroll
            for (int mt = 0; mt < 4; mt++)
                #pragma unroll
                for (int nt = 0; nt < 4; nt++) {
                    mma_tf32(acc[mt][nt], ah[mt], bh[nt]);
                    mma_tf32(acc[mt][nt], ah[mt], bl[nt]);
                    mma_tf32(acc[mt][nt], al[mt], bh[nt]);
                }
        }

        if (more) {
            CP_WAIT0();
        }
        __syncthreads();
    }

    // ---- epilogue ----
    const int g  = lane >> 2;
    const int tg = lane & 3;
    #pragma unroll
    for (int mt = 0; mt < 4; mt++) {
        #pragma unroll
        for (int nt = 0; nt < 4; nt++) {
            int row = m0 + wm * 64 + mt * 16 + g;
            int col = n0 + wn * 32 + nt * 8 + 2 * tg;
            #pragma unroll
            for (int hh = 0; hh < 2; hh++) {
                int r = row + hh * 8;
                float2 v;
                v.x = acc[mt][nt][2 * hh + 0];
                v.y = acc[mt][nt][2 * hh + 1];
                if (EPI >= 1) { v.x += bias[col]; v.y += bias[col + 1]; }
                if (EPI == 1) { v.x = fmaxf(v.x, 0.f); v.y = fmaxf(v.y, 0.f); }
                if (EPI == 2) {
                    const float2 rr = *(const float2*)(res + (size_t)r * ldc + col);
                    v.x += rr.x; v.y += rr.y;
                }
                *(float2*)(C + (size_t)r * ldc + col) = v;
            }
        }
    }
}

// ================= flash attention (fp32, proven, fused-QKV layout) =================
#define FA_STR  68
#define FA_SMEM (3 * 64 * FA_STR * 4)
#define QKV_LD  (3 * D_MODEL)

__global__ __launch_bounds__(128) void flash_attn_kernel(const float* __restrict__ QKV,
                                                         float* __restrict__ O)
{
    extern __shared__ float sm[];
    float* Qs = sm;
    float* Ks = sm + 64 * FA_STR;
    float* Vs = sm + 2 * 64 * FA_STR;

    const int tid = threadIdx.x;
    const int ty  = tid >> 3;
    const int tx  = tid & 7;
    const int b   = blockIdx.z;
    const int h   = blockIdx.y;
    const int q0  = blockIdx.x * 64;
    const size_t rowb = (size_t)b * SEQ;
    const size_t qoff = rowb * QKV_LD + (size_t)h * HDIM;

    for (int v = tid; v < 1024; v += 128) {
        int r = v >> 4, c = (v & 15) << 2;
        float4 t = *(const float4*)(QKV + qoff + (size_t)(q0 + r) * QKV_LD + c);
        t.x *= 8.f; t.y *= 8.f; t.z *= 8.f; t.w *= 8.f;
        *(float4*)&Qs[r * FA_STR + c] = t;
    }

    float m[4], l[4], o[4][8];
    #pragma unroll
    for (int i = 0; i < 4; i++) {
        m[i] = -1e30f; l[i] = 0.f;
        #pragma unroll
        for (int j = 0; j < 8; j++) o[i][j] = 0.f;
    }

    for (int kt = 0; kt < SEQ; kt += 64) {
        __syncthreads();
        for (int v = tid; v < 1024; v += 128) {
            int r = v >> 4, c = (v & 15) << 2;
            *(float4*)&Ks[r * FA_STR + c] =
                *(const float4*)(QKV + qoff + D_MODEL + (size_t)(kt + r) * QKV_LD + c);
            *(float4*)&Vs[r * FA_STR + c] =
                *(const float4*)(QKV + qoff + 2 * D_MODEL + (size_t)(kt + r) * QKV_LD + c);
        }
        __syncthreads();

        float s[4][8];
        #pragma unroll
        for (int i = 0; i < 4; i++)
            #pragma unroll
            for (int j = 0; j < 8; j++) s[i][j] = 0.f;

        #pragma unroll 4
        for (int k = 0; k < 64; k++) {
            float qa[4], kb[8];
            #pragma unroll
            for (int i = 0; i < 4; i++) qa[i] = Qs[(ty + 16 * i) * FA_STR + k];
            #pragma unroll
            for (int j = 0; j < 8; j++) kb[j] = Ks[(tx + 8 * j) * FA_STR + k];
            #pragma unroll
            for (int i = 0; i < 4; i++)
                #pragma unroll
                for (int j = 0; j < 8; j++) s[i][j] = fmaf(qa[i], kb[j], s[i][j]);
        }

        __syncthreads();

        #pragma unroll
        for (int i = 0; i < 4; i++) {
            float mx = s[i][0];
            #pragma unroll
            for (int j = 1; j < 8; j++) mx = fmaxf(mx, s[i][j]);
            #pragma unroll
            for (int off = 1; off < 8; off <<= 1)
                mx = fmaxf(mx, __shfl_xor_sync(0xffffffffu, mx, off));
            float mn   = fmaxf(m[i], mx);
            float corr = __expf(m[i] - mn);
            float rs = 0.f;
            #pragma unroll
            for (int j = 0; j < 8; j++) { s[i][j] = __expf(s[i][j] - mn); rs += s[i][j]; }
            #pragma unroll
            for (int off = 1; off < 8; off <<= 1)
                rs += __shfl_xor_sync(0xffffffffu, rs, off);
            l[i] = l[i] * corr + rs;
            m[i] = mn;
            #pragma unroll
            for (int j = 0; j < 8; j++) o[i][j] *= corr;
            #pragma unroll
            for (int j = 0; j < 8; j++) Ks[(ty + 16 * i) * FA_STR + tx + 8 * j] = s[i][j];
        }
        __syncthreads();

        #pragma unroll 4
        for (int c = 0; c < 64; c++) {
            float pr[4], vb[8];
            #pragma unroll
            for (int i = 0; i < 4; i++) pr[i] = Ks[(ty + 16 * i) * FA_STR + c];
            #pragma unroll
            for (int j = 0; j < 8; j++) vb[j] = Vs[c * FA_STR + tx + 8 * j];
            #pragma unroll
            for (int i = 0; i < 4; i++)
                #pragma unroll
                for (int j = 0; j < 8; j++) o[i][j] = fmaf(pr[i], vb[j], o[i][j]);
        }
    }

    const size_t obase = rowb * D_MODEL + (size_t)h * HDIM;
    #pragma unroll
    for (int i = 0; i < 4; i++) {
        float inv = 1.f / l[i];
        size_t rowoff = obase + (size_t)(q0 + ty + 16 * i) * D_MODEL;
        #pragma unroll
        for (int j = 0; j < 8; j++) O[rowoff + tx + 8 * j] = o[i][j] * inv;
    }
}

// ================= layernorm =================
__global__ __launch_bounds__(256) void ln_kernel(const float* __restrict__ A,
                                                 const float* __restrict__ Add,
                                                 const float* __restrict__ g,
                                                 const float* __restrict__ bb,
                                                 float* __restrict__ out,
                                                 int useAdd)
{
    __shared__ float red[8];
    const int row = blockIdx.x;
    const size_t off = (size_t)row * D_MODEL;
    const int tid = threadIdx.x;

    float x[4]; float s = 0.f;
    #pragma unroll
    for (int i = 0; i < 4; i++) {
        int c = tid + 256 * i;
        float v = A[off + c];
        if (useAdd) v += Add[off + c];
        x[i] = v; s += v;
    }
    #pragma unroll
    for (int o = 16; o > 0; o >>= 1) s += __shfl_xor_sync(0xffffffffu, s, o);
    if ((tid & 31) == 0) red[tid >> 5] = s;
    __syncthreads();
    float tot = 0.f;
    #pragma unroll
    for (int i = 0; i < 8; i++) tot += red[i];
    const float mean = tot * (1.0f / 1024.0f);

    float vs = 0.f;
    #pragma unroll
    for (int i = 0; i < 4; i++) { float d = x[i] - mean; vs += d * d; }
    #pragma unroll
    for (int o = 16; o > 0; o >>= 1) vs += __shfl_xor_sync(0xffffffffu, vs, o);
    __syncthreads();
    if ((tid & 31) == 0) red[tid >> 5] = vs;
    __syncthreads();
    float vt = 0.f;
    #pragma unroll
    for (int i = 0; i < 8; i++) vt += red[i];
    const float inv = rsqrtf(vt * (1.0f / 1024.0f) + 1e-5f);

    #pragma unroll
    for (int i = 0; i < 4; i++) {
        int c = tid + 256 * i;
        out[off + c] = (x[i] - mean) * inv * g[c] + bb[c];
    }
}

// ================= launch =================
extern "C" void kernel_launch(void* const* d_in, const int* in_sizes, int n_in,
                              void* d_out, int out_size)
{
    const float* input = (const float*)d_in[0];
    const float* pos   = (const float*)d_in[1];
    const float* Wq    = (const float*)d_in[2];
    const float* Wk    = (const float*)d_in[3];
    const float* Wv    = (const float*)d_in[4];
    const float* W1    = (const float*)d_in[5];
    const float* b1    = (const float*)d_in[6];
    const float* W2    = (const float*)d_in[7];
    const float* b2    = (const float*)d_in[8];
    const float* ln1g  = (const float*)d_in[9];
    const float* ln1b  = (const float*)d_in[10];
    const float* ln2g  = (const float*)d_in[11];
    const float* ln2b  = (const float*)d_in[12];
    float* out = (float*)d_out;

    float *qkin, *QKV, *attn, *x1, *ff1, *h, *WqkvT, *W1T, *W2T;
    cudaGetSymbolAddress((void**)&qkin,  g_qkin);
    cudaGetSymbolAddress((void**)&QKV,   g_QKV);
    cudaGetSymbolAddress((void**)&attn,  g_attn);
    cudaGetSymbolAddress((void**)&x1,    g_x1);
    cudaGetSymbolAddress((void**)&ff1,   g_ff1);
    cudaGetSymbolAddress((void**)&h,     g_h);
    cudaGetSymbolAddress((void**)&WqkvT, g_WqkvT);
    cudaGetSymbolAddress((void**)&W1T,   g_W1T);
    cudaGetSymbolAddress((void**)&W2T,   g_W2T);

    cudaFuncSetAttribute(flash_attn_kernel,
                         cudaFuncAttributeMaxDynamicSharedMemorySize, FA_SMEM);
    cudaFuncSetAttribute(mma_gemm_kernel<0, true>,
                         cudaFuncAttributeMaxDynamicSharedMemorySize, MG_SMEM);
    cudaFuncSetAttribute(mma_gemm_kernel<1, false>,
                         cudaFuncAttributeMaxDynamicSharedMemorySize, MG_SMEM);
    cudaFuncSetAttribute(mma_gemm_kernel<2, false>,
                         cudaFuncAttributeMaxDynamicSharedMemorySize, MG_SMEM);

    // 0) weight transposes
    transpose_kernel<<<dim3(32, 32),  256>>>(Wq, WqkvT,                   1024, 1024);
    transpose_kernel<<<dim3(32, 32),  256>>>(Wk, WqkvT + 1024 * 1024,     1024, 1024);
    transpose_kernel<<<dim3(32, 32),  256>>>(Wv, WqkvT + 2 * 1024 * 1024, 1024, 1024);
    transpose_kernel<<<dim3(128, 32), 256>>>(W1, W1T, 1024, 4096);
    transpose_kernel<<<dim3(32, 128), 256>>>(W2, W2T, 4096, 1024);

    // 1) qk_in = input + pos
    {
        int n4 = ROWS * D_MODEL / 4;
        add_kernel<<<(n4 + 255) / 256, 256>>>(input, pos, qkin, n4);
    }

    // 2) fused QKV projection
    mma_gemm_kernel<0, true><<<dim3(24, 32), 256, MG_SMEM>>>(
        qkin, input, WqkvT, nullptr, nullptr, QKV, 1024, 3 * D_MODEL);

    // 3) attention
    {
        dim3 ga(SEQ / 64, HEADS, BATCH);
        flash_attn_kernel<<<ga, 128, FA_SMEM>>>(QKV, attn);
    }

    // 4) x1 = LN(input + attn)
    ln_kernel<<<ROWS, 256>>>(input, attn, ln1g, ln1b, x1, 1);

    // 5) ff1 = relu(x1 @ W1 + b1)
    mma_gemm_kernel<1, false><<<dim3(32, 32), 256, MG_SMEM>>>(
        x1, nullptr, W1T, b1, nullptr, ff1, 1024, FF_DIM);

    // 6) h = ff1 @ W2 + b2 + x1
    mma_gemm_kernel<2, false><<<dim3(8, 32), 256, MG_SMEM>>>(
        ff1, nullptr, W2T, b2, x1, h, 4096, D_MODEL);

    // 7) out = LN(h)
    ln_kernel<<<ROWS, 256>>>(h, h, ln2g, ln2b, out, 0);
}

// round 6
// speedup vs baseline: 2.4445x; 1.5097x over previous
#include <cuda_runtime.h>
#include <cuda_bf16.h>
#include <math.h>
#include <stdint.h>

#define D_MODEL 1024
#define FF_DIM  4096
#define BATCH   4
#define SEQ     1024
#define HEADS   16
#define HDIM    64
#define ROWS    (BATCH*SEQ)   // 4096

typedef __nv_bfloat16 bf16;

// ================= scratch =================
__device__ float g_QKV  [ROWS*3*D_MODEL];   // [4096, 3072]: Q | K | V (fp32 for FA)
__device__ float g_attn [ROWS*D_MODEL];
__device__ float g_x1   [ROWS*D_MODEL];
__device__ float g_h    [ROWS*D_MODEL];

__device__ bf16 g_qkinH[ROWS*D_MODEL];      // input+pos, split
__device__ bf16 g_qkinL[ROWS*D_MODEL];
__device__ bf16 g_inH  [ROWS*D_MODEL];      // input, split (for V)
__device__ bf16 g_inL  [ROWS*D_MODEL];
__device__ bf16 g_x1H  [ROWS*D_MODEL];
__device__ bf16 g_x1L  [ROWS*D_MODEL];
__device__ bf16 g_ff1H [ROWS*FF_DIM];
__device__ bf16 g_ff1L [ROWS*FF_DIM];
__device__ bf16 g_WqkvTH[3*D_MODEL*D_MODEL];  // [3072,1024] K-major
__device__ bf16 g_WqkvTL[3*D_MODEL*D_MODEL];
__device__ bf16 g_W1TH [FF_DIM*D_MODEL];      // [4096,1024]
__device__ bf16 g_W1TL [FF_DIM*D_MODEL];
__device__ bf16 g_W2TH [D_MODEL*FF_DIM];      // [1024,4096]
__device__ bf16 g_W2TL [D_MODEL*FF_DIM];

// ================= helpers =================
__device__ __forceinline__ uint32_t smem_u32(const void* p) {
    uint32_t a;
    asm("{ .reg .u64 t; cvta.to.shared.u64 t, %1; cvt.u32.u64 %0, t; }" : "=r"(a) : "l"(p));
    return a;
}
__device__ __forceinline__ void splitbf(float x, bf16& hi, bf16& lo) {
    hi = __float2bfloat16_rn(x);
    lo = __float2bfloat16_rn(x - __bfloat162float(hi));
}
__device__ __forceinline__ void ldsm_x4(uint32_t* r, uint32_t addr) {
    asm volatile("ldmatrix.sync.aligned.m8n8.x4.shared.b16 {%0,%1,%2,%3}, [%4];"
                 : "=r"(r[0]), "=r"(r[1]), "=r"(r[2]), "=r"(r[3]) : "r"(addr));
}
__device__ __forceinline__ void ldsm_x2(uint32_t* r, uint32_t addr) {
    asm volatile("ldmatrix.sync.aligned.m8n8.x2.shared.b16 {%0,%1}, [%2];"
                 : "=r"(r[0]), "=r"(r[1]) : "r"(addr));
}
__device__ __forceinline__ void mma_bf16(float* d, const uint32_t* a, const uint32_t* b) {
    asm volatile("mma.sync.aligned.m16n8k16.row.col.f32.bf16.bf16.f32 "
                 "{%0,%1,%2,%3}, {%4,%5,%6,%7}, {%8,%9}, {%0,%1,%2,%3};"
                 : "+f"(d[0]), "+f"(d[1]), "+f"(d[2]), "+f"(d[3])
                 : "r"(a[0]), "r"(a[1]), "r"(a[2]), "r"(a[3]), "r"(b[0]), "r"(b[1]));
}
#define CP_ASYNC16(dst, src) \
    asm volatile("cp.async.cg.shared.global [%0], [%1], 16;" :: "r"(dst), "l"(src))
#define CP_COMMIT() asm volatile("cp.async.commit_group;" ::: "memory")
#define CP_WAIT0()  asm volatile("cp.async.wait_group 0;" ::: "memory")
#define CP_WAIT1()  asm volatile("cp.async.wait_group 1;" ::: "memory")

// ================= transpose + split: out[c][r] = split(in[r][c]) =================
__global__ __launch_bounds__(256) void transpose_split_kernel(const float* __restrict__ in,
                                                              bf16* __restrict__ hi,
                                                              bf16* __restrict__ lo,
                                                              int R, int C)
{
    __shared__ float t[32][33];
    const int cb = blockIdx.x * 32, rb = blockIdx.y * 32;
    const int tx = threadIdx.x & 31, ty = threadIdx.x >> 5;
    #pragma unroll
    for (int i = 0; i < 4; i++)
        t[ty + 8 * i][tx] = in[(size_t)(rb + ty + 8 * i) * C + cb + tx];
    __syncthreads();
    #pragma unroll
    for (int i = 0; i < 4; i++) {
        float x = t[tx][ty + 8 * i];
        bf16 h, l; splitbf(x, h, l);
        size_t o = (size_t)(cb + ty + 8 * i) * R + rb + tx;
        hi[o] = h; lo[o] = l;
    }
}

// ================= elementwise split (optionally a+b) =================
__global__ __launch_bounds__(256) void split_kernel(const float* __restrict__ a,
                                                    const float* __restrict__ b,
                                                    bf16* __restrict__ hi,
                                                    bf16* __restrict__ lo, int n4)
{
    int i = blockIdx.x * blockDim.x + threadIdx.x;
    if (i < n4) {
        float4 x = ((const float4*)a)[i];
        if (b) {
            float4 y = ((const float4*)b)[i];
            x.x += y.x; x.y += y.y; x.z += y.z; x.w += y.w;
        }
        bf16 h[4], l[4];
        splitbf(x.x, h[0], l[0]); splitbf(x.y, h[1], l[1]);
        splitbf(x.z, h[2], l[2]); splitbf(x.w, h[3], l[3]);
        ((uint2*)hi)[i] = *(uint2*)h;
        ((uint2*)lo)[i] = *(uint2*)l;
    }
}

// ================= mma.sync bf16 GEMM (3xBF16 split, pre-split operands) =================
// C[4096, ldc] tile [m0:+128, n0:+128] = A[4096,K] @ Bt[ldc,K]^T, fp32-accurate
// CTA 128x128x32, 256 thr, 8 warps (2m x 4n), warp tile 64x32. 3-stage cp.async.
// EPI: 0 = fp32 C; 1 = +bias+relu -> write bf16 hi/lo (CH/CL); 2 = +bias+res -> fp32 C
#define KC       32
#define ROWB     80                         // 64B data + 16B pad (LDSM conflict-free)
#define TILE_B   (128 * ROWB)               // 10240 B
#define STAGE_B  (4 * TILE_B)               // Ahi|Alo|Bhi|Blo = 40960 B
#define MG_SMEM  (3 * STAGE_B)              // 122880 B

template<int EPI, bool QKVSEL>
__global__ void __launch_bounds__(256, 1)
mma_gemm_kernel(const bf16* __restrict__ A0H, const bf16* __restrict__ A0L,
                const bf16* __restrict__ A1H, const bf16* __restrict__ A1L,
                const bf16* __restrict__ BH,  const bf16* __restrict__ BL,
                const float* __restrict__ bias, const float* __restrict__ res,
                float* __restrict__ C, bf16* __restrict__ CH, bf16* __restrict__ CL,
                int K, int ldc)
{
    extern __shared__ uint32_t dsm[];
    const int tid  = threadIdx.x;
    const int wid  = tid >> 5;
    const int lane = tid & 31;
    const int m0   = blockIdx.y * 128;
    const int n0   = blockIdx.x * 128;
    const int wm   = wid & 1;
    const int wn   = wid >> 1;

    const bf16* AH = (QKVSEL && n0 >= 2 * D_MODEL) ? A1H : A0H;
    const bf16* AL = (QKVSEL && n0 >= 2 * D_MODEL) ? A1L : A0L;

    const bf16* tp0 = AH + (size_t)m0 * K;
    const bf16* tp1 = AL + (size_t)m0 * K;
    const bf16* tp2 = BH + (size_t)n0 * K;
    const bf16* tp3 = BL + (size_t)n0 * K;

    const uint32_t sbase = smem_u32(dsm);

    float acc[4][4][4];
    #pragma unroll
    for (int i = 0; i < 4; i++)
        #pragma unroll
        for (int j = 0; j < 4; j++)
            #pragma unroll
            for (int q = 0; q < 4; q++) acc[i][j][q] = 0.f;

    const int T = K / KC;

    auto STAGE = [&](int p, int kc) {
        const uint32_t sb = sbase + p * STAGE_B;
        #pragma unroll
        for (int tile = 0; tile < 4; tile++) {
            const bf16* base = (tile == 0) ? tp0 : (tile == 1) ? tp1 : (tile == 2) ? tp2 : tp3;
            #pragma unroll
            for (int j = 0; j < 2; j++) {
                int c = tid + 256 * j;         // 0..511
                int r = c >> 2, ch = c & 3;    // row, 16B chunk
                CP_ASYNC16(sb + tile * TILE_B + r * ROWB + ch * 16,
                           base + (size_t)r * K + kc + ch * 8);
            }
        }
        CP_COMMIT();
    };

    STAGE(0, 0);
    STAGE(1, KC);

    // ldmatrix lane address components (16B-granule geometry validated in R4)
    const int a_r = wm * 64 + (lane & 15);          // + mt*16
    const int a_c = ((lane >> 4) & 1) * 16;         // byte offset; + ks*32
    const int b_r = wn * 32 + (lane & 7);           // + nt*8
    const int b_c = ((lane >> 3) & 1) * 16;         // byte offset; + ks*32

    for (int t = 0; t < T; t++) {
        const int p = t % 3;
        if (t + 1 < T) { CP_WAIT1(); } else { CP_WAIT0(); }
        __syncthreads();
        if (t + 2 < T) STAGE((t + 2) % 3, (t + 2) * KC);

        const uint32_t Ahb = sbase + p * STAGE_B;
        const uint32_t Alb = Ahb + TILE_B;
        const uint32_t Bhb = Alb + TILE_B;
        const uint32_t Blb = Bhb + TILE_B;

        #pragma unroll
        for (int ks = 0; ks < 2; ks++) {
            uint32_t ah[4][4], al[4][4], bh[4][2], bl[4][2];
            #pragma unroll
            for (int mt = 0; mt < 4; mt++) {
                uint32_t ro = (a_r + mt * 16) * ROWB + ks * 32 + a_c;
                ldsm_x4(ah[mt], Ahb + ro);
                ldsm_x4(al[mt], Alb + ro);
            }
            #pragma unroll
            for (int nt = 0; nt < 4; nt++) {
                uint32_t ro = (b_r + nt * 8) * ROWB + ks * 32 + b_c;
                ldsm_x2(bh[nt], Bhb + ro);
                ldsm_x2(bl[nt], Blb + ro);
            }
            #pragma unroll
            for (int mt = 0; mt < 4; mt++)
                #pragma unroll
                for (int nt = 0; nt < 4; nt++) {
                    mma_bf16(acc[mt][nt], ah[mt], bh[nt]);
                    mma_bf16(acc[mt][nt], ah[mt], bl[nt]);
                    mma_bf16(acc[mt][nt], al[mt], bh[nt]);
                }
        }
        __syncthreads();
    }

    // ---- epilogue ----
    const int g  = lane >> 2;
    const int tg = lane & 3;
    #pragma unroll
    for (int mt = 0; mt < 4; mt++) {
        #pragma unroll
        for (int nt = 0; nt < 4; nt++) {
            int row = m0 + wm * 64 + mt * 16 + g;
            int col = n0 + wn * 32 + nt * 8 + 2 * tg;
            #pragma unroll
            for (int hh = 0; hh < 2; hh++) {
                int r = row + hh * 8;
                float2 v;
                v.x = acc[mt][nt][2 * hh + 0];
                v.y = acc[mt][nt][2 * hh + 1];
                if (EPI >= 1) { v.x += bias[col]; v.y += bias[col + 1]; }
                if (EPI == 1) {
                    v.x = fmaxf(v.x, 0.f); v.y = fmaxf(v.y, 0.f);
                    bf16 h0, l0, h1, l1;
                    splitbf(v.x, h0, l0); splitbf(v.y, h1, l1);
                    bf16 hp[2] = {h0, h1}, lp[2] = {l0, l1};
                    *(uint32_t*)(CH + (size_t)r * ldc + col) = *(uint32_t*)hp;
                    *(uint32_t*)(CL + (size_t)r * ldc + col) = *(uint32_t*)lp;
                } else {
                    if (EPI == 2) {
                        const float2 rr = *(const float2*)(res + (size_t)r * ldc + col);
                        v.x += rr.x; v.y += rr.y;
                    }
                    *(float2*)(C + (size_t)r * ldc + col) = v;
                }
            }
        }
    }
}

// ================= flash attention (fp32, proven, fused-QKV layout) =================
#define FA_STR  68
#define FA_SMEM (3 * 64 * FA_STR * 4)
#define QKV_LD  (3 * D_MODEL)

__global__ __launch_bounds__(128) void flash_attn_kernel(const float* __restrict__ QKV,
                                                         float* __restrict__ O)
{
    extern __shared__ float sm[];
    float* Qs = sm;
    float* Ks = sm + 64 * FA_STR;
    float* Vs = sm + 2 * 64 * FA_STR;

    const int tid = threadIdx.x;
    const int ty  = tid >> 3;
    const int tx  = tid & 7;
    const int b   = blockIdx.z;
    const int h   = blockIdx.y;
    const int q0  = blockIdx.x * 64;
    const size_t rowb = (size_t)b * SEQ;
    const size_t qoff = rowb * QKV_LD + (size_t)h * HDIM;

    for (int v = tid; v < 1024; v += 128) {
        int r = v >> 4, c = (v & 15) << 2;
        float4 t = *(const float4*)(QKV + qoff + (size_t)(q0 + r) * QKV_LD + c);
        t.x *= 8.f; t.y *= 8.f; t.z *= 8.f; t.w *= 8.f;
        *(float4*)&Qs[r * FA_STR + c] = t;
    }

    float m[4], l[4], o[4][8];
    #pragma unroll
    for (int i = 0; i < 4; i++) {
        m[i] = -1e30f; l[i] = 0.f;
        #pragma unroll
        for (int j = 0; j < 8; j++) o[i][j] = 0.f;
    }

    for (int kt = 0; kt < SEQ; kt += 64) {
        __syncthreads();
        for (int v = tid; v < 1024; v += 128) {
            int r = v >> 4, c = (v & 15) << 2;
            *(float4*)&Ks[r * FA_STR + c] =
                *(const float4*)(QKV + qoff + D_MODEL + (size_t)(kt + r) * QKV_LD + c);
            *(float4*)&Vs[r * FA_STR + c] =
                *(const float4*)(QKV + qoff + 2 * D_MODEL + (size_t)(kt + r) * QKV_LD + c);
        }
        __syncthreads();

        float s[4][8];
        #pragma unroll
        for (int i = 0; i < 4; i++)
            #pragma unroll
            for (int j = 0; j < 8; j++) s[i][j] = 0.f;

        #pragma unroll 4
        for (int k = 0; k < 64; k++) {
            float qa[4], kb[8];
            #pragma unroll
            for (int i = 0; i < 4; i++) qa[i] = Qs[(ty + 16 * i) * FA_STR + k];
            #pragma unroll
            for (int j = 0; j < 8; j++) kb[j] = Ks[(tx + 8 * j) * FA_STR + k];
            #pragma unroll
            for (int i = 0; i < 4; i++)
                #pragma unroll
                for (int j = 0; j < 8; j++) s[i][j] = fmaf(qa[i], kb[j], s[i][j]);
        }

        __syncthreads();

        #pragma unroll
        for (int i = 0; i < 4; i++) {
            float mx = s[i][0];
            #pragma unroll
            for (int j = 1; j < 8; j++) mx = fmaxf(mx, s[i][j]);
            #pragma unroll
            for (int off = 1; off < 8; off <<= 1)
                mx = fmaxf(mx, __shfl_xor_sync(0xffffffffu, mx, off));
            float mn   = fmaxf(m[i], mx);
            float corr = __expf(m[i] - mn);
            float rs = 0.f;
            #pragma unroll
            for (int j = 0; j < 8; j++) { s[i][j] = __expf(s[i][j] - mn); rs += s[i][j]; }
            #pragma unroll
            for (int off = 1; off < 8; off <<= 1)
                rs += __shfl_xor_sync(0xffffffffu, rs, off);
            l[i] = l[i] * corr + rs;
            m[i] = mn;
            #pragma unroll
            for (int j = 0; j < 8; j++) o[i][j] *= corr;
            #pragma unroll
            for (int j = 0; j < 8; j++) Ks[(ty + 16 * i) * FA_STR + tx + 8 * j] = s[i][j];
        }
        __syncthreads();

        #pragma unroll 4
        for (int c = 0; c < 64; c++) {
            float pr[4], vb[8];
            #pragma unroll
            for (int i = 0; i < 4; i++) pr[i] = Ks[(ty + 16 * i) * FA_STR + c];
            #pragma unroll
            for (int j = 0; j < 8; j++) vb[j] = Vs[c * FA_STR + tx + 8 * j];
            #pragma unroll
            for (int i = 0; i < 4; i++)
                #pragma unroll
                for (int j = 0; j < 8; j++) o[i][j] = fmaf(pr[i], vb[j], o[i][j]);
        }
    }

    const size_t obase = rowb * D_MODEL + (size_t)h * HDIM;
    #pragma unroll
    for (int i = 0; i < 4; i++) {
        float inv = 1.f / l[i];
        size_t rowoff = obase + (size_t)(q0 + ty + 16 * i) * D_MODEL;
        #pragma unroll
        for (int j = 0; j < 8; j++) O[rowoff + tx + 8 * j] = o[i][j] * inv;
    }
}

// ================= layernorm (optional residual, optional bf16 hi/lo out) =================
__global__ __launch_bounds__(256) void ln_kernel(const float* __restrict__ A,
                                                 const float* __restrict__ Add,
                                                 const float* __restrict__ g,
                                                 const float* __restrict__ bb,
                                                 float* __restrict__ out,
                                                 bf16* __restrict__ outH,
                                                 bf16* __restrict__ outL,
                                                 int useAdd)
{
    __shared__ float red[8];
    const int row = blockIdx.x;
    const size_t off = (size_t)row * D_MODEL;
    const int tid = threadIdx.x;

    float x[4]; float s = 0.f;
    #pragma unroll
    for (int i = 0; i < 4; i++) {
        int c = tid + 256 * i;
        float v = A[off + c];
        if (useAdd) v += Add[off + c];
        x[i] = v; s += v;
    }
    #pragma unroll
    for (int o = 16; o > 0; o >>= 1) s += __shfl_xor_sync(0xffffffffu, s, o);
    if ((tid & 31) == 0) red[tid >> 5] = s;
    __syncthreads();
    float tot = 0.f;
    #pragma unroll
    for (int i = 0; i < 8; i++) tot += red[i];
    const float mean = tot * (1.0f / 1024.0f);

    float vs = 0.f;
    #pragma unroll
    for (int i = 0; i < 4; i++) { float d = x[i] - mean; vs += d * d; }
    #pragma unroll
    for (int o = 16; o > 0; o >>= 1) vs += __shfl_xor_sync(0xffffffffu, vs, o);
    __syncthreads();
    if ((tid & 31) == 0) red[tid >> 5] = vs;
    __syncthreads();
    float vt = 0.f;
    #pragma unroll
    for (int i = 0; i < 8; i++) vt += red[i];
    const float inv = rsqrtf(vt * (1.0f / 1024.0f) + 1e-5f);

    #pragma unroll
    for (int i = 0; i < 4; i++) {
        int c = tid + 256 * i;
        float v = (x[i] - mean) * inv * g[c] + bb[c];
        out[off + c] = v;
        if (outH) {
            bf16 h, l; splitbf(v, h, l);
            outH[off + c] = h; outL[off + c] = l;
        }
    }
}

// ================= launch =================
extern "C" void kernel_launch(void* const* d_in, const int* in_sizes, int n_in,
                              void* d_out, int out_size)
{
    const float* input = (const float*)d_in[0];
    const float* pos   = (const float*)d_in[1];
    const float* Wq    = (const float*)d_in[2];
    const float* Wk    = (const float*)d_in[3];
    const float* Wv    = (const float*)d_in[4];
    const float* W1    = (const float*)d_in[5];
    const float* b1    = (const float*)d_in[6];
    const float* W2    = (const float*)d_in[7];
    const float* b2    = (const float*)d_in[8];
    const float* ln1g  = (const float*)d_in[9];
    const float* ln1b  = (const float*)d_in[10];
    const float* ln2g  = (const float*)d_in[11];
    const float* ln2b  = (const float*)d_in[12];
    float* out = (float*)d_out;

    float *QKV, *attn, *x1, *h;
    bf16 *qkinH, *qkinL, *inH, *inL, *x1H, *x1L, *ff1H, *ff1L;
    bf16 *WqkvTH, *WqkvTL, *W1TH, *W1TL, *W2TH, *W2TL;
    cudaGetSymbolAddress((void**)&QKV,    g_QKV);
    cudaGetSymbolAddress((void**)&attn,   g_attn);
    cudaGetSymbolAddress((void**)&x1,     g_x1);
    cudaGetSymbolAddress((void**)&h,      g_h);
    cudaGetSymbolAddress((void**)&qkinH,  g_qkinH);
    cudaGetSymbolAddress((void**)&qkinL,  g_qkinL);
    cudaGetSymbolAddress((void**)&inH,    g_inH);
    cudaGetSymbolAddress((void**)&inL,    g_inL);
    cudaGetSymbolAddress((void**)&x1H,    g_x1H);
    cudaGetSymbolAddress((void**)&x1L,    g_x1L);
    cudaGetSymbolAddress((void**)&ff1H,   g_ff1H);
    cudaGetSymbolAddress((void**)&ff1L,   g_ff1L);
    cudaGetSymbolAddress((void**)&WqkvTH, g_WqkvTH);
    cudaGetSymbolAddress((void**)&WqkvTL, g_WqkvTL);
    cudaGetSymbolAddress((void**)&W1TH,   g_W1TH);
    cudaGetSymbolAddress((void**)&W1TL,   g_W1TL);
    cudaGetSymbolAddress((void**)&W2TH,   g_W2TH);
    cudaGetSymbolAddress((void**)&W2TL,   g_W2TL);

    cudaFuncSetAttribute(flash_attn_kernel,
                         cudaFuncAttributeMaxDynamicSharedMemorySize, FA_SMEM);
    cudaFuncSetAttribute(mma_gemm_kernel<0, true>,
                         cudaFuncAttributeMaxDynamicSharedMemorySize, MG_SMEM);
    cudaFuncSetAttribute(mma_gemm_kernel<1, false>,
                         cudaFuncAttributeMaxDynamicSharedMemorySize, MG_SMEM);
    cudaFuncSetAttribute(mma_gemm_kernel<2, false>,
                         cudaFuncAttributeMaxDynamicSharedMemorySize, MG_SMEM);

    // 0) weight transpose + split
    transpose_split_kernel<<<dim3(32, 32),  256>>>(Wq, WqkvTH,                   WqkvTL,                   1024, 1024);
    transpose_split_kernel<<<dim3(32, 32),  256>>>(Wk, WqkvTH + 1024 * 1024,     WqkvTL + 1024 * 1024,     1024, 1024);
    transpose_split_kernel<<<dim3(32, 32),  256>>>(Wv, WqkvTH + 2 * 1024 * 1024, WqkvTL + 2 * 1024 * 1024, 1024, 1024);
    transpose_split_kernel<<<dim3(128, 32), 256>>>(W1, W1TH, W1TL, 1024, 4096);
    transpose_split_kernel<<<dim3(32, 128), 256>>>(W2, W2TH, W2TL, 4096, 1024);

    // 1) activation splits: qkin = input+pos; in = input (for V)
    {
        int n4 = ROWS * D_MODEL / 4;
        split_kernel<<<(n4 + 255) / 256, 256>>>(input, pos,     qkinH, qkinL, n4);
        split_kernel<<<(n4 + 255) / 256, 256>>>(input, nullptr, inH,   inL,   n4);
    }

    // 2) fused QKV projection (fp32 out for FA)
    mma_gemm_kernel<0, true><<<dim3(24, 32), 256, MG_SMEM>>>(
        qkinH, qkinL, inH, inL, WqkvTH, WqkvTL,
        nullptr, nullptr, QKV, nullptr, nullptr, 1024, 3 * D_MODEL);

    // 3) attention
    {
        dim3 ga(SEQ / 64, HEADS, BATCH);
        flash_attn_kernel<<<ga, 128, FA_SMEM>>>(QKV, attn);
    }

    // 4) x1 = LN(input + attn), with bf16 split out
    ln_kernel<<<ROWS, 256>>>(input, attn, ln1g, ln1b, x1, x1H, x1L, 1);

    // 5) ff1 = relu(x1 @ W1 + b1) -> bf16 hi/lo directly
    mma_gemm_kernel<1, false><<<dim3(32, 32), 256, MG_SMEM>>>(
        x1H, x1L, nullptr, nullptr, W1TH, W1TL,
        b1, nullptr, nullptr, ff1H, ff1L, 1024, FF_DIM);

    // 6) h = ff1 @ W2 + b2 + x1 (fp32)
    mma_gemm_kernel<2, false><<<dim3(8, 32), 256, MG_SMEM>>>(
        ff1H, ff1L, nullptr, nullptr, W2TH, W2TL,
        b2, x1, h, nullptr, nullptr, 4096, D_MODEL);

    // 7) out = LN(h)
    ln_kernel<<<ROWS, 256>>>(h, h, ln2g, ln2b, out, nullptr, nullptr, 0);
}

// round 7
// speedup vs baseline: 3.0129x; 1.2325x over previous
#include <cuda_runtime.h>
#include <cuda_bf16.h>
#include <math.h>
#include <stdint.h>

#define D_MODEL 1024
#define FF_DIM  4096
#define BATCH   4
#define SEQ     1024
#define HEADS   16
#define HDIM    64
#define ROWS    (BATCH*SEQ)   // 4096

typedef __nv_bfloat16 bf16;

// ================= scratch =================
__device__ float g_attn [ROWS*D_MODEL];
__device__ float g_x1   [ROWS*D_MODEL];
__device__ float g_h    [ROWS*D_MODEL];

__device__ bf16 g_qkinH[ROWS*D_MODEL];
__device__ bf16 g_qkinL[ROWS*D_MODEL];
__device__ bf16 g_inH  [ROWS*D_MODEL];
__device__ bf16 g_inL  [ROWS*D_MODEL];
__device__ bf16 g_x1H  [ROWS*D_MODEL];
__device__ bf16 g_x1L  [ROWS*D_MODEL];
__device__ bf16 g_ff1H [ROWS*FF_DIM];
__device__ bf16 g_ff1L [ROWS*FF_DIM];
// per-head split QKV: [b*16+h][seq][64]
__device__ bf16 g_QH[ROWS*D_MODEL];
__device__ bf16 g_QL[ROWS*D_MODEL];
__device__ bf16 g_KH[ROWS*D_MODEL];
__device__ bf16 g_KL[ROWS*D_MODEL];
__device__ bf16 g_VH[ROWS*D_MODEL];
__device__ bf16 g_VL[ROWS*D_MODEL];

__device__ bf16 g_WqkvTH[3*D_MODEL*D_MODEL];
__device__ bf16 g_WqkvTL[3*D_MODEL*D_MODEL];
__device__ bf16 g_W1TH [FF_DIM*D_MODEL];
__device__ bf16 g_W1TL [FF_DIM*D_MODEL];
__device__ bf16 g_W2TH [D_MODEL*FF_DIM];
__device__ bf16 g_W2TL [D_MODEL*FF_DIM];

// ================= helpers =================
__device__ __forceinline__ uint32_t smem_u32(const void* p) {
    uint32_t a;
    asm("{ .reg .u64 t; cvta.to.shared.u64 t, %1; cvt.u32.u64 %0, t; }" : "=r"(a) : "l"(p));
    return a;
}
__device__ __forceinline__ void splitbf(float x, bf16& hi, bf16& lo) {
    hi = __float2bfloat16_rn(x);
    lo = __float2bfloat16_rn(x - __bfloat162float(hi));
}
__device__ __forceinline__ void packsplit(float c0, float c1, uint32_t& hi, uint32_t& lo) {
    __nv_bfloat162 hp = __floats2bfloat162_rn(c0, c1);
    float r0 = c0 - __bfloat162float(hp.x);
    float r1 = c1 - __bfloat162float(hp.y);
    __nv_bfloat162 lp = __floats2bfloat162_rn(r0, r1);
    hi = *(uint32_t*)&hp; lo = *(uint32_t*)&lp;
}
__device__ __forceinline__ void ldsm_x4(uint32_t* r, uint32_t addr) {
    asm volatile("ldmatrix.sync.aligned.m8n8.x4.shared.b16 {%0,%1,%2,%3}, [%4];"
                 : "=r"(r[0]), "=r"(r[1]), "=r"(r[2]), "=r"(r[3]) : "r"(addr));
}
__device__ __forceinline__ void ldsm_x2(uint32_t* r, uint32_t addr) {
    asm volatile("ldmatrix.sync.aligned.m8n8.x2.shared.b16 {%0,%1}, [%2];"
                 : "=r"(r[0]), "=r"(r[1]) : "r"(addr));
}
__device__ __forceinline__ void ldsm_x2_t(uint32_t* r, uint32_t addr) {
    asm volatile("ldmatrix.sync.aligned.m8n8.x2.trans.shared.b16 {%0,%1}, [%2];"
                 : "=r"(r[0]), "=r"(r[1]) : "r"(addr));
}
__device__ __forceinline__ void mma_bf16(float* d, const uint32_t* a, const uint32_t* b) {
    asm volatile("mma.sync.aligned.m16n8k16.row.col.f32.bf16.bf16.f32 "
                 "{%0,%1,%2,%3}, {%4,%5,%6,%7}, {%8,%9}, {%0,%1,%2,%3};"
                 : "+f"(d[0]), "+f"(d[1]), "+f"(d[2]), "+f"(d[3])
                 : "r"(a[0]), "r"(a[1]), "r"(a[2]), "r"(a[3]), "r"(b[0]), "r"(b[1]));
}
#define CP_ASYNC16(dst, src) \
    asm volatile("cp.async.cg.shared.global [%0], [%1], 16;" :: "r"(dst), "l"(src))
#define CP_COMMIT() asm volatile("cp.async.commit_group;" ::: "memory")
#define CP_WAIT0()  asm volatile("cp.async.wait_group 0;" ::: "memory")
#define CP_WAIT1()  asm volatile("cp.async.wait_group 1;" ::: "memory")

// ================= transpose + split =================
__global__ __launch_bounds__(256) void transpose_split_kernel(const float* __restrict__ in,
                                                              bf16* __restrict__ hi,
                                                              bf16* __restrict__ lo,
                                                              int R, int C)
{
    __shared__ float t[32][33];
    const int cb = blockIdx.x * 32, rb = blockIdx.y * 32;
    const int tx = threadIdx.x & 31, ty = threadIdx.x >> 5;
    #pragma unroll
    for (int i = 0; i < 4; i++)
        t[ty + 8 * i][tx] = in[(size_t)(rb + ty + 8 * i) * C + cb + tx];
    __syncthreads();
    #pragma unroll
    for (int i = 0; i < 4; i++) {
        float x = t[tx][ty + 8 * i];
        bf16 h, l; splitbf(x, h, l);
        size_t o = (size_t)(cb + ty + 8 * i) * R + rb + tx;
        hi[o] = h; lo[o] = l;
    }
}

// ================= elementwise split =================
__global__ __launch_bounds__(256) void split_kernel(const float* __restrict__ a,
                                                    const float* __restrict__ b,
                                                    bf16* __restrict__ hi,
                                                    bf16* __restrict__ lo, int n4)
{
    int i = blockIdx.x * blockDim.x + threadIdx.x;
    if (i < n4) {
        float4 x = ((const float4*)a)[i];
        if (b) {
            float4 y = ((const float4*)b)[i];
            x.x += y.x; x.y += y.y; x.z += y.z; x.w += y.w;
        }
        bf16 h[4], l[4];
        splitbf(x.x, h[0], l[0]); splitbf(x.y, h[1], l[1]);
        splitbf(x.z, h[2], l[2]); splitbf(x.w, h[3], l[3]);
        ((uint2*)hi)[i] = *(uint2*)h;
        ((uint2*)lo)[i] = *(uint2*)l;
    }
}

// ================= mma.sync bf16 GEMM (3xBF16) =================
// EPI: 0 = fp32 C; 1 = +bias+relu -> bf16 hi/lo; 2 = +bias+res -> fp32;
//      3 = QKV: scale Q by 8, split, per-head layout into QH..VL
#define KC       32
#define ROWB     80
#define TILE_B   (128 * ROWB)
#define STAGE_B  (4 * TILE_B)
#define MG_SMEM  (3 * STAGE_B)

template<int EPI, bool QKVSEL>
__global__ void __launch_bounds__(256, 1)
mma_gemm_kernel(const bf16* __restrict__ A0H, const bf16* __restrict__ A0L,
                const bf16* __restrict__ A1H, const bf16* __restrict__ A1L,
                const bf16* __restrict__ BH,  const bf16* __restrict__ BL,
                const float* __restrict__ bias, const float* __restrict__ res,
                float* __restrict__ C, bf16* __restrict__ CH, bf16* __restrict__ CL,
                bf16* __restrict__ oQH, bf16* __restrict__ oQL,
                bf16* __restrict__ oKH, bf16* __restrict__ oKL,
                bf16* __restrict__ oVH, bf16* __restrict__ oVL,
                int K, int ldc)
{
    extern __shared__ uint32_t dsm[];
    const int tid  = threadIdx.x;
    const int wid  = tid >> 5;
    const int lane = tid & 31;
    const int m0   = blockIdx.y * 128;
    const int n0   = blockIdx.x * 128;
    const int wm   = wid & 1;
    const int wn   = wid >> 1;

    const bf16* AH = (QKVSEL && n0 >= 2 * D_MODEL) ? A1H : A0H;
    const bf16* AL = (QKVSEL && n0 >= 2 * D_MODEL) ? A1L : A0L;

    const bf16* tp0 = AH + (size_t)m0 * K;
    const bf16* tp1 = AL + (size_t)m0 * K;
    const bf16* tp2 = BH + (size_t)n0 * K;
    const bf16* tp3 = BL + (size_t)n0 * K;

    const uint32_t sbase = smem_u32(dsm);

    float acc[4][4][4];
    #pragma unroll
    for (int i = 0; i < 4; i++)
        #pragma unroll
        for (int j = 0; j < 4; j++)
            #pragma unroll
            for (int q = 0; q < 4; q++) acc[i][j][q] = 0.f;

    const int T = K / KC;

    auto STAGE = [&](int p, int kc) {
        const uint32_t sb = sbase + p * STAGE_B;
        #pragma unroll
        for (int tile = 0; tile < 4; tile++) {
            const bf16* base = (tile == 0) ? tp0 : (tile == 1) ? tp1 : (tile == 2) ? tp2 : tp3;
            #pragma unroll
            for (int j = 0; j < 2; j++) {
                int c = tid + 256 * j;
                int r = c >> 2, ch = c & 3;
                CP_ASYNC16(sb + tile * TILE_B + r * ROWB + ch * 16,
                           base + (size_t)r * K + kc + ch * 8);
            }
        }
        CP_COMMIT();
    };

    STAGE(0, 0);
    STAGE(1, KC);

    const int a_r = wm * 64 + (lane & 15);
    const int a_c = ((lane >> 4) & 1) * 16;
    const int b_r = wn * 32 + (lane & 7);
    const int b_c = ((lane >> 3) & 1) * 16;

    for (int t = 0; t < T; t++) {
        const int p = t % 3;
        if (t + 1 < T) { CP_WAIT1(); } else { CP_WAIT0(); }
        __syncthreads();
        if (t + 2 < T) STAGE((t + 2) % 3, (t + 2) * KC);

        const uint32_t Ahb = sbase + p * STAGE_B;
        const uint32_t Alb = Ahb + TILE_B;
        const uint32_t Bhb = Alb + TILE_B;
        const uint32_t Blb = Bhb + TILE_B;

        #pragma unroll
        for (int ks = 0; ks < 2; ks++) {
            uint32_t ah[4][4], al[4][4], bh[4][2], bl[4][2];
            #pragma unroll
            for (int mt = 0; mt < 4; mt++) {
                uint32_t ro = (a_r + mt * 16) * ROWB + ks * 32 + a_c;
                ldsm_x4(ah[mt], Ahb + ro);
                ldsm_x4(al[mt], Alb + ro);
            }
            #pragma unroll
            for (int nt = 0; nt < 4; nt++) {
                uint32_t ro = (b_r + nt * 8) * ROWB + ks * 32 + b_c;
                ldsm_x2(bh[nt], Bhb + ro);
                ldsm_x2(bl[nt], Blb + ro);
            }
            #pragma unroll
            for (int mt = 0; mt < 4; mt++)
                #pragma unroll
                for (int nt = 0; nt < 4; nt++) {
                    mma_bf16(acc[mt][nt], ah[mt], bh[nt]);
                    mma_bf16(acc[mt][nt], ah[mt], bl[nt]);
                    mma_bf16(acc[mt][nt], al[mt], bh[nt]);
                }
        }
        __syncthreads();
    }

    // ---- epilogue ----
    const int g  = lane >> 2;
    const int tg = lane & 3;
    #pragma unroll
    for (int mt = 0; mt < 4; mt++) {
        #pragma unroll
        for (int nt = 0; nt < 4; nt++) {
            int row = m0 + wm * 64 + mt * 16 + g;
            int col = n0 + wn * 32 + nt * 8 + 2 * tg;
            #pragma unroll
            for (int hh = 0; hh < 2; hh++) {
                int r = row + hh * 8;
                float2 v;
                v.x = acc[mt][nt][2 * hh + 0];
                v.y = acc[mt][nt][2 * hh + 1];
                if (EPI == 1 || EPI == 2) { v.x += bias[col]; v.y += bias[col + 1]; }
                if (EPI == 1) {
                    v.x = fmaxf(v.x, 0.f); v.y = fmaxf(v.y, 0.f);
                    bf16 h0, l0, h1, l1;
                    splitbf(v.x, h0, l0); splitbf(v.y, h1, l1);
                    bf16 hp[2] = {h0, h1}, lp[2] = {l0, l1};
                    *(uint32_t*)(CH + (size_t)r * ldc + col) = *(uint32_t*)hp;
                    *(uint32_t*)(CL + (size_t)r * ldc + col) = *(uint32_t*)lp;
                } else if (EPI == 3) {
                    int sec = col >> 10;
                    int hd  = (col >> 6) & 15;
                    int d   = col & 63;
                    int bb  = r >> 10, s = r & 1023;
                    size_t o = ((size_t)(bb * HEADS + hd) * SEQ + s) * HDIM + d;
                    float sc = (sec == 0) ? 8.f : 1.f;
                    v.x *= sc; v.y *= sc;
                    bf16 h0, l0, h1, l1;
                    splitbf(v.x, h0, l0); splitbf(v.y, h1, l1);
                    bf16 hp[2] = {h0, h1}, lp[2] = {l0, l1};
                    bf16* H = (sec == 0) ? oQH : (sec == 1) ? oKH : oVH;
                    bf16* L = (sec == 0) ? oQL : (sec == 1) ? oKL : oVL;
                    *(uint32_t*)(H + o) = *(uint32_t*)hp;
                    *(uint32_t*)(L + o) = *(uint32_t*)lp;
                } else {
                    if (EPI == 2) {
                        const float2 rr = *(const float2*)(res + (size_t)r * ldc + col);
                        v.x += rr.x; v.y += rr.y;
                    }
                    *(float2*)(C + (size_t)r * ldc + col) = v;
                }
            }
        }
    }
}

// ================= tensor-core flash attention (3xBF16) =================
// grid (16 qtiles, 16 heads, 4 batch), 128 thr (4 warps, 16 rows each).
#define FT_ROWB 144
#define FT_TILE (64 * FT_ROWB)                 // 9216
#define FT_SMEM (2 * FT_TILE + 8 * FT_TILE)    // 92160

__global__ void __launch_bounds__(128, 2)
flash_attn_tc_kernel(const bf16* __restrict__ QH, const bf16* __restrict__ QL,
                     const bf16* __restrict__ KH, const bf16* __restrict__ KL,
                     const bf16* __restrict__ VH, const bf16* __restrict__ VL,
                     float* __restrict__ O)
{
    extern __shared__ char smc[];
    const uint32_t sb = smem_u32(smc);
    const int tid = threadIdx.x, wid = tid >> 5, lane = tid & 31;
    const int g = lane >> 2, tg = lane & 3;
    const int q0 = blockIdx.x * 64;
    const int bh = blockIdx.z * HEADS + blockIdx.y;
    const size_t hb = (size_t)bh * SEQ * HDIM;

    const uint32_t sQH = sb, sQL = sb + FT_TILE;

    auto STAGE_KV = [&](int p, int kt) {
        uint32_t st = sb + 2 * FT_TILE + p * 4 * FT_TILE;
        const bf16* bases[4] = {KH + hb, KL + hb, VH + hb, VL + hb};
        #pragma unroll
        for (int tile = 0; tile < 4; tile++) {
            #pragma unroll
            for (int j = 0; j < 4; j++) {
                int c = tid + 128 * j;
                int r = c >> 3, ch = c & 7;
                CP_ASYNC16(st + tile * FT_TILE + r * FT_ROWB + ch * 16,
                           bases[tile] + (size_t)(kt * 64 + r) * HDIM + ch * 8);
            }
        }
        CP_COMMIT();
    };

    // stage Q + KV0 as group 0; KV1 as group 1
    {
        const bf16* qb[2] = {QH + hb, QL + hb};
        #pragma unroll
        for (int tile = 0; tile < 2; tile++)
            #pragma unroll
            for (int j = 0; j < 4; j++) {
                int c = tid + 128 * j;
                int r = c >> 3, ch = c & 7;
                CP_ASYNC16((tile ? sQL : sQH) + r * FT_ROWB + ch * 16,
                           qb[tile] + (size_t)(q0 + r) * HDIM + ch * 8);
            }
        // KV0 in same group
        uint32_t st = sb + 2 * FT_TILE;
        const bf16* bases[4] = {KH + hb, KL + hb, VH + hb, VL + hb};
        #pragma unroll
        for (int tile = 0; tile < 4; tile++)
            #pragma unroll
            for (int j = 0; j < 4; j++) {
                int c = tid + 128 * j;
                int r = c >> 3, ch = c & 7;
                CP_ASYNC16(st + tile * FT_TILE + r * FT_ROWB + ch * 16,
                           bases[tile] + (size_t)r * HDIM + ch * 8);
            }
        CP_COMMIT();
    }
    STAGE_KV(1, 1);

    CP_WAIT1();
    __syncthreads();

    // preload Q fragments
    uint32_t qh[4][4], ql[4][4];
    const int a_r = wid * 16 + (lane & 15);
    const int a_c = ((lane >> 4) & 1) * 16;
    #pragma unroll
    for (int ks = 0; ks < 4; ks++) {
        ldsm_x4(qh[ks], sQH + a_r * FT_ROWB + ks * 32 + a_c);
        ldsm_x4(ql[ks], sQL + a_r * FT_ROWB + ks * 32 + a_c);
    }

    float acco[8][4];
    #pragma unroll
    for (int nt = 0; nt < 8; nt++)
        #pragma unroll
        for (int q = 0; q < 4; q++) acco[nt][q] = 0.f;
    float mrow[2] = {-1e30f, -1e30f};
    float lrow[2] = {0.f, 0.f};

    const int b_r = lane & 7;
    const int b_c = ((lane >> 3) & 1) * 16;
    const int v_r = (lane & 7) + ((lane >> 3) & 1) * 8;

    const int T = SEQ / 64;
    for (int t = 0; t < T; t++) {
        if (t > 0) {
            if (t + 1 < T) { CP_WAIT1(); } else { CP_WAIT0(); }
            __syncthreads();
        }
        const uint32_t st  = sb + 2 * FT_TILE + (t & 1) * 4 * FT_TILE;
        const uint32_t sKH = st, sKL = st + FT_TILE;
        const uint32_t sVH = st + 2 * FT_TILE, sVL = st + 3 * FT_TILE;

        // ---- S = (8Q) K^T ----
        float accs[8][4];
        #pragma unroll
        for (int nt = 0; nt < 8; nt++)
            #pragma unroll
            for (int q = 0; q < 4; q++) accs[nt][q] = 0.f;

        #pragma unroll
        for (int ks = 0; ks < 4; ks++) {
            #pragma unroll
            for (int nt = 0; nt < 8; nt++) {
                uint32_t kh2[2], kl2[2];
                uint32_t ro = (nt * 8 + b_r) * FT_ROWB + ks * 32 + b_c;
                ldsm_x2(kh2, sKH + ro);
                ldsm_x2(kl2, sKL + ro);
                mma_bf16(accs[nt], qh[ks], kh2);
                mma_bf16(accs[nt], qh[ks], kl2);
                mma_bf16(accs[nt], ql[ks], kh2);
            }
        }

        // ---- online softmax ----
        #pragma unroll
        for (int h = 0; h < 2; h++) {
            float mx = accs[0][2 * h];
            #pragma unroll
            for (int nt = 0; nt < 8; nt++)
                mx = fmaxf(mx, fmaxf(accs[nt][2 * h], accs[nt][2 * h + 1]));
            mx = fmaxf(mx, __shfl_xor_sync(0xffffffffu, mx, 1));
            mx = fmaxf(mx, __shfl_xor_sync(0xffffffffu, mx, 2));
            float mn = fmaxf(mrow[h], mx);
            float corr = __expf(mrow[h] - mn);
            float sum = 0.f;
            #pragma unroll
            for (int nt = 0; nt < 8; nt++) {
                float e0 = __expf(accs[nt][2 * h] - mn);
                float e1 = __expf(accs[nt][2 * h + 1] - mn);
                accs[nt][2 * h] = e0; accs[nt][2 * h + 1] = e1;
                sum += e0 + e1;
            }
            sum += __shfl_xor_sync(0xffffffffu, sum, 1);
            sum += __shfl_xor_sync(0xffffffffu, sum, 2);
            lrow[h] = lrow[h] * corr + sum;
            mrow[h] = mn;
            #pragma unroll
            for (int nt = 0; nt < 8; nt++) {
                acco[nt][2 * h] *= corr; acco[nt][2 * h + 1] *= corr;
            }
        }

        // ---- O += P V ----
        #pragma unroll
        for (int ks = 0; ks < 4; ks++) {
            uint32_t ph[4], pl[4];
            packsplit(accs[2 * ks][0],     accs[2 * ks][1],     ph[0], pl[0]);
            packsplit(accs[2 * ks][2],     accs[2 * ks][3],     ph[1], pl[1]);
            packsplit(accs[2 * ks + 1][0], accs[2 * ks + 1][1], ph[2], pl[2]);
            packsplit(accs[2 * ks + 1][2], accs[2 * ks + 1][3], ph[3], pl[3]);
            #pragma unroll
            for (int nt = 0; nt < 8; nt++) {
                uint32_t vh2[2], vl2[2];
                uint32_t ro = (ks * 16 + v_r) * FT_ROWB + nt * 16;
                ldsm_x2_t(vh2, sVH + ro);
                ldsm_x2_t(vl2, sVL + ro);
                mma_bf16(acco[nt], ph, vh2);
                mma_bf16(acco[nt], ph, vl2);
                mma_bf16(acco[nt], pl, vh2);
            }
        }

        __syncthreads();
        if (t + 2 < T) STAGE_KV(t & 1, t + 2);
    }

    // ---- write O ----
    #pragma unroll
    for (int h = 0; h < 2; h++) {
        float inv = 1.f / lrow[h];
        int s = q0 + wid * 16 + g + h * 8;
        float* orow = O + ((size_t)(blockIdx.z * SEQ + s)) * D_MODEL + blockIdx.y * HDIM;
        #pragma unroll
        for (int nt = 0; nt < 8; nt++) {
            float2 v;
            v.x = acco[nt][2 * h] * inv;
            v.y = acco[nt][2 * h + 1] * inv;
            *(float2*)(orow + nt * 8 + 2 * tg) = v;
        }
    }
}

// ================= layernorm =================
__global__ __launch_bounds__(256) void ln_kernel(const float* __restrict__ A,
                                                 const float* __restrict__ Add,
                                                 const float* __restrict__ g,
                                                 const float* __restrict__ bb,
                                                 float* __restrict__ out,
                                                 bf16* __restrict__ outH,
                                                 bf16* __restrict__ outL,
                                                 int useAdd)
{
    __shared__ float red[8];
    const int row = blockIdx.x;
    const size_t off = (size_t)row * D_MODEL;
    const int tid = threadIdx.x;

    float x[4]; float s = 0.f;
    #pragma unroll
    for (int i = 0; i < 4; i++) {
        int c = tid + 256 * i;
        float v = A[off + c];
        if (useAdd) v += Add[off + c];
        x[i] = v; s += v;
    }
    #pragma unroll
    for (int o = 16; o > 0; o >>= 1) s += __shfl_xor_sync(0xffffffffu, s, o);
    if ((tid & 31) == 0) red[tid >> 5] = s;
    __syncthreads();
    float tot = 0.f;
    #pragma unroll
    for (int i = 0; i < 8; i++) tot += red[i];
    const float mean = tot * (1.0f / 1024.0f);

    float vs = 0.f;
    #pragma unroll
    for (int i = 0; i < 4; i++) { float d = x[i] - mean; vs += d * d; }
    #pragma unroll
    for (int o = 16; o > 0; o >>= 1) vs += __shfl_xor_sync(0xffffffffu, vs, o);
    __syncthreads();
    if ((tid & 31) == 0) red[tid >> 5] = vs;
    __syncthreads();
    float vt = 0.f;
    #pragma unroll
    for (int i = 0; i < 8; i++) vt += red[i];
    const float inv = rsqrtf(vt * (1.0f / 1024.0f) + 1e-5f);

    #pragma unroll
    for (int i = 0; i < 4; i++) {
        int c = tid + 256 * i;
        float v = (x[i] - mean) * inv * g[c] + bb[c];
        out[off + c] = v;
        if (outH) {
            bf16 h, l; splitbf(v, h, l);
            outH[off + c] = h; outL[off + c] = l;
        }
    }
}

// ================= launch =================
extern "C" void kernel_launch(void* const* d_in, const int* in_sizes, int n_in,
                              void* d_out, int out_size)
{
    const float* input = (const float*)d_in[0];
    const float* pos   = (const float*)d_in[1];
    const float* Wq    = (const float*)d_in[2];
    const float* Wk    = (const float*)d_in[3];
    const float* Wv    = (const float*)d_in[4];
    const float* W1    = (const float*)d_in[5];
    const float* b1    = (const float*)d_in[6];
    const float* W2    = (const float*)d_in[7];
    const float* b2    = (const float*)d_in[8];
    const float* ln1g  = (const float*)d_in[9];
    const float* ln1b  = (const float*)d_in[10];
    const float* ln2g  = (const float*)d_in[11];
    const float* ln2b  = (const float*)d_in[12];
    float* out = (float*)d_out;

    float *attn, *x1, *h;
    bf16 *qkinH, *qkinL, *inH, *inL, *x1H, *x1L, *ff1H, *ff1L;
    bf16 *QH, *QL, *KHp, *KLp, *VHp, *VLp;
    bf16 *WqkvTH, *WqkvTL, *W1TH, *W1TL, *W2TH, *W2TL;
    cudaGetSymbolAddress((void**)&attn,   g_attn);
    cudaGetSymbolAddress((void**)&x1,     g_x1);
    cudaGetSymbolAddress((void**)&h,      g_h);
    cudaGetSymbolAddress((void**)&qkinH,  g_qkinH);
    cudaGetSymbolAddress((void**)&qkinL,  g_qkinL);
    cudaGetSymbolAddress((void**)&inH,    g_inH);
    cudaGetSymbolAddress((void**)&inL,    g_inL);
    cudaGetSymbolAddress((void**)&x1H,    g_x1H);
    cudaGetSymbolAddress((void**)&x1L,    g_x1L);
    cudaGetSymbolAddress((void**)&ff1H,   g_ff1H);
    cudaGetSymbolAddress((void**)&ff1L,   g_ff1L);
    cudaGetSymbolAddress((void**)&QH,     g_QH);
    cudaGetSymbolAddress((void**)&QL,     g_QL);
    cudaGetSymbolAddress((void**)&KHp,    g_KH);
    cudaGetSymbolAddress((void**)&KLp,    g_KL);
    cudaGetSymbolAddress((void**)&VHp,    g_VH);
    cudaGetSymbolAddress((void**)&VLp,    g_VL);
    cudaGetSymbolAddress((void**)&WqkvTH, g_WqkvTH);
    cudaGetSymbolAddress((void**)&WqkvTL, g_WqkvTL);
    cudaGetSymbolAddress((void**)&W1TH,   g_W1TH);
    cudaGetSymbolAddress((void**)&W1TL,   g_W1TL);
    cudaGetSymbolAddress((void**)&W2TH,   g_W2TH);
    cudaGetSymbolAddress((void**)&W2TL,   g_W2TL);

    cudaFuncSetAttribute(flash_attn_tc_kernel,
                         cudaFuncAttributeMaxDynamicSharedMemorySize, FT_SMEM);
    cudaFuncSetAttribute(mma_gemm_kernel<3, true>,
                         cudaFuncAttributeMaxDynamicSharedMemorySize, MG_SMEM);
    cudaFuncSetAttribute(mma_gemm_kernel<1, false>,
                         cudaFuncAttributeMaxDynamicSharedMemorySize, MG_SMEM);
    cudaFuncSetAttribute(mma_gemm_kernel<2, false>,
                         cudaFuncAttributeMaxDynamicSharedMemorySize, MG_SMEM);

    // 0) weight transpose + split
    transpose_split_kernel<<<dim3(32, 32),  256>>>(Wq, WqkvTH,                   WqkvTL,                   1024, 1024);
    transpose_split_kernel<<<dim3(32, 32),  256>>>(Wk, WqkvTH + 1024 * 1024,     WqkvTL + 1024 * 1024,     1024, 1024);
    transpose_split_kernel<<<dim3(32, 32),  256>>>(Wv, WqkvTH + 2 * 1024 * 1024, WqkvTL + 2 * 1024 * 1024, 1024, 1024);
    transpose_split_kernel<<<dim3(128, 32), 256>>>(W1, W1TH, W1TL, 1024, 4096);
    transpose_split_kernel<<<dim3(32, 128), 256>>>(W2, W2TH, W2TL, 4096, 1024);

    // 1) activation splits
    {
        int n4 = ROWS * D_MODEL / 4;
        split_kernel<<<(n4 + 255) / 256, 256>>>(input, pos,     qkinH, qkinL, n4);
        split_kernel<<<(n4 + 255) / 256, 256>>>(input, nullptr, inH,   inL,   n4);
    }

    // 2) fused QKV projection -> per-head split bf16 (Q pre-scaled by 8)
    mma_gemm_kernel<3, true><<<dim3(24, 32), 256, MG_SMEM>>>(
        qkinH, qkinL, inH, inL, WqkvTH, WqkvTL,
        nullptr, nullptr, nullptr, nullptr, nullptr,
        QH, QL, KHp, KLp, VHp, VLp, 1024, 3 * D_MODEL);

    // 3) tensor-core attention
    flash_attn_tc_kernel<<<dim3(SEQ / 64, HEADS, BATCH), 128, FT_SMEM>>>(
        QH, QL, KHp, KLp, VHp, VLp, attn);

    // 4) x1 = LN(input + attn)
    ln_kernel<<<ROWS, 256>>>(input, attn, ln1g, ln1b, x1, x1H, x1L, 1);

    // 5) ff1 = relu(x1 @ W1 + b1) -> bf16 hi/lo
    mma_gemm_kernel<1, false><<<dim3(32, 32), 256, MG_SMEM>>>(
        x1H, x1L, nullptr, nullptr, W1TH, W1TL,
        b1, nullptr, nullptr, ff1H, ff1L,
        nullptr, nullptr, nullptr, nullptr, nullptr, nullptr, 1024, FF_DIM);

    // 6) h = ff1 @ W2 + b2 + x1
    mma_gemm_kernel<2, false><<<dim3(8, 32), 256, MG_SMEM>>>(
        ff1H, ff1L, nullptr, nullptr, W2TH, W2TL,
        b2, x1, h, nullptr, nullptr,
        nullptr, nullptr, nullptr, nullptr, nullptr, nullptr, 4096, D_MODEL);

    // 7) out = LN(h)
    ln_kernel<<<ROWS, 256>>>(h, h, ln2g, ln2b, out, nullptr, nullptr, 0);
}

// round 8
// speedup vs baseline: 3.4654x; 1.1502x over previous
#include <cuda_runtime.h>
#include <cuda_bf16.h>
#include <math.h>
#include <stdint.h>

#define D_MODEL 1024
#define FF_DIM  4096
#define BATCH   4
#define SEQ     1024
#define HEADS   16
#define HDIM    64
#define ROWS    (BATCH*SEQ)   // 4096

typedef __nv_bfloat16 bf16;

// ================= scratch =================
__device__ float g_attn [ROWS*D_MODEL];
__device__ float g_x1   [ROWS*D_MODEL];
__device__ float g_h    [ROWS*D_MODEL];

__device__ bf16 g_qkinH[ROWS*D_MODEL];
__device__ bf16 g_qkinL[ROWS*D_MODEL];
__device__ bf16 g_inH  [ROWS*D_MODEL];
__device__ bf16 g_inL  [ROWS*D_MODEL];
__device__ bf16 g_x1H  [ROWS*D_MODEL];
__device__ bf16 g_x1L  [ROWS*D_MODEL];
__device__ bf16 g_ff1H [ROWS*FF_DIM];
__device__ bf16 g_ff1L [ROWS*FF_DIM];
// per-head split QKV: [b*16+h][seq][64]
__device__ bf16 g_QH[ROWS*D_MODEL];
__device__ bf16 g_QL[ROWS*D_MODEL];
__device__ bf16 g_KH[ROWS*D_MODEL];
__device__ bf16 g_KL[ROWS*D_MODEL];
__device__ bf16 g_VH[ROWS*D_MODEL];
__device__ bf16 g_VL[ROWS*D_MODEL];

__device__ bf16 g_WqkvTH[3*D_MODEL*D_MODEL];
__device__ bf16 g_WqkvTL[3*D_MODEL*D_MODEL];
__device__ bf16 g_W1TH [FF_DIM*D_MODEL];
__device__ bf16 g_W1TL [FF_DIM*D_MODEL];
__device__ bf16 g_W2TH [D_MODEL*FF_DIM];
__device__ bf16 g_W2TL [D_MODEL*FF_DIM];

// ================= helpers =================
__device__ __forceinline__ uint32_t smem_u32(const void* p) {
    uint32_t a;
    asm("{ .reg .u64 t; cvta.to.shared.u64 t, %1; cvt.u32.u64 %0, t; }" : "=r"(a) : "l"(p));
    return a;
}
__device__ __forceinline__ void splitbf(float x, bf16& hi, bf16& lo) {
    hi = __float2bfloat16_rn(x);
    lo = __float2bfloat16_rn(x - __bfloat162float(hi));
}
__device__ __forceinline__ void packsplit(float c0, float c1, uint32_t& hi, uint32_t& lo) {
    __nv_bfloat162 hp = __floats2bfloat162_rn(c0, c1);
    float r0 = c0 - __bfloat162float(hp.x);
    float r1 = c1 - __bfloat162float(hp.y);
    __nv_bfloat162 lp = __floats2bfloat162_rn(r0, r1);
    hi = *(uint32_t*)&hp; lo = *(uint32_t*)&lp;
}
__device__ __forceinline__ void ldsm_x4(uint32_t* r, uint32_t addr) {
    asm volatile("ldmatrix.sync.aligned.m8n8.x4.shared.b16 {%0,%1,%2,%3}, [%4];"
                 : "=r"(r[0]), "=r"(r[1]), "=r"(r[2]), "=r"(r[3]) : "r"(addr));
}
__device__ __forceinline__ void ldsm_x2(uint32_t* r, uint32_t addr) {
    asm volatile("ldmatrix.sync.aligned.m8n8.x2.shared.b16 {%0,%1}, [%2];"
                 : "=r"(r[0]), "=r"(r[1]) : "r"(addr));
}
__device__ __forceinline__ void ldsm_x2_t(uint32_t* r, uint32_t addr) {
    asm volatile("ldmatrix.sync.aligned.m8n8.x2.trans.shared.b16 {%0,%1}, [%2];"
                 : "=r"(r[0]), "=r"(r[1]) : "r"(addr));
}
__device__ __forceinline__ void mma_bf16(float* d, const uint32_t* a, const uint32_t* b) {
    asm volatile("mma.sync.aligned.m16n8k16.row.col.f32.bf16.bf16.f32 "
                 "{%0,%1,%2,%3}, {%4,%5,%6,%7}, {%8,%9}, {%0,%1,%2,%3};"
                 : "+f"(d[0]), "+f"(d[1]), "+f"(d[2]), "+f"(d[3])
                 : "r"(a[0]), "r"(a[1]), "r"(a[2]), "r"(a[3]), "r"(b[0]), "r"(b[1]));
}
#define CP_ASYNC16(dst, src) \
    asm volatile("cp.async.cg.shared.global [%0], [%1], 16;" :: "r"(dst), "l"(src))
#define CP_COMMIT() asm volatile("cp.async.commit_group;" ::: "memory")
#define CP_WAIT0()  asm volatile("cp.async.wait_group 0;" ::: "memory")
#define CP_WAIT1()  asm volatile("cp.async.wait_group 1;" ::: "memory")

// ================= transpose + split =================
__global__ __launch_bounds__(256) void transpose_split_kernel(const float* __restrict__ in,
                                                              bf16* __restrict__ hi,
                                                              bf16* __restrict__ lo,
                                                              int R, int C)
{
    __shared__ float t[32][33];
    const int cb = blockIdx.x * 32, rb = blockIdx.y * 32;
    const int tx = threadIdx.x & 31, ty = threadIdx.x >> 5;
    #pragma unroll
    for (int i = 0; i < 4; i++)
        t[ty + 8 * i][tx] = in[(size_t)(rb + ty + 8 * i) * C + cb + tx];
    __syncthreads();
    #pragma unroll
    for (int i = 0; i < 4; i++) {
        float x = t[tx][ty + 8 * i];
        bf16 h, l; splitbf(x, h, l);
        size_t o = (size_t)(cb + ty + 8 * i) * R + rb + tx;
        hi[o] = h; lo[o] = l;
    }
}

// ================= merged elementwise split: (a+b) and (a) =================
__global__ __launch_bounds__(256) void split2_kernel(const float* __restrict__ a,
                                                     const float* __restrict__ b,
                                                     bf16* __restrict__ hiAB,
                                                     bf16* __restrict__ loAB,
                                                     bf16* __restrict__ hiA,
                                                     bf16* __restrict__ loA, int n4)
{
    int i = blockIdx.x * blockDim.x + threadIdx.x;
    if (i < n4) {
        float4 x = ((const float4*)a)[i];
        float4 y = ((const float4*)b)[i];
        bf16 h[4], l[4];
        splitbf(x.x, h[0], l[0]); splitbf(x.y, h[1], l[1]);
        splitbf(x.z, h[2], l[2]); splitbf(x.w, h[3], l[3]);
        ((uint2*)hiA)[i] = *(uint2*)h;
        ((uint2*)loA)[i] = *(uint2*)l;
        x.x += y.x; x.y += y.y; x.z += y.z; x.w += y.w;
        splitbf(x.x, h[0], l[0]); splitbf(x.y, h[1], l[1]);
        splitbf(x.z, h[2], l[2]); splitbf(x.w, h[3], l[3]);
        ((uint2*)hiAB)[i] = *(uint2*)h;
        ((uint2*)loAB)[i] = *(uint2*)l;
    }
}

// ================= mma.sync bf16 GEMM (3xBF16), KC=64, 3-stage =================
// EPI: 0 = fp32 C; 1 = +bias+relu -> bf16 hi/lo; 2 = +bias+res -> fp32;
//      3 = QKV: scale Q by 8, split, per-head layout into QH..VL
#define KC       64
#define ROWB     144                        // 128B data + 16B pad
#define TILE_B   (128 * ROWB)               // 18432
#define STAGE_B  (4 * TILE_B)               // 73728
#define MG_SMEM  (3 * STAGE_B)              // 221184

template<int EPI, bool QKVSEL>
__global__ void __launch_bounds__(256, 1)
mma_gemm_kernel(const bf16* __restrict__ A0H, const bf16* __restrict__ A0L,
                const bf16* __restrict__ A1H, const bf16* __restrict__ A1L,
                const bf16* __restrict__ BH,  const bf16* __restrict__ BL,
                const float* __restrict__ bias, const float* __restrict__ res,
                float* __restrict__ C, bf16* __restrict__ CH, bf16* __restrict__ CL,
                bf16* __restrict__ oQH, bf16* __restrict__ oQL,
                bf16* __restrict__ oKH, bf16* __restrict__ oKL,
                bf16* __restrict__ oVH, bf16* __restrict__ oVL,
                int K, int ldc)
{
    extern __shared__ uint32_t dsm[];
    const int tid  = threadIdx.x;
    const int wid  = tid >> 5;
    const int lane = tid & 31;
    const int m0   = blockIdx.y * 128;
    const int n0   = blockIdx.x * 128;
    const int wm   = wid & 1;
    const int wn   = wid >> 1;

    const bf16* AH = (QKVSEL && n0 >= 2 * D_MODEL) ? A1H : A0H;
    const bf16* AL = (QKVSEL && n0 >= 2 * D_MODEL) ? A1L : A0L;

    const bf16* tp0 = AH + (size_t)m0 * K;
    const bf16* tp1 = AL + (size_t)m0 * K;
    const bf16* tp2 = BH + (size_t)n0 * K;
    const bf16* tp3 = BL + (size_t)n0 * K;

    const uint32_t sbase = smem_u32(dsm);

    float acc[4][4][4];
    #pragma unroll
    for (int i = 0; i < 4; i++)
        #pragma unroll
        for (int j = 0; j < 4; j++)
            #pragma unroll
            for (int q = 0; q < 4; q++) acc[i][j][q] = 0.f;

    const int T = K / KC;

    auto STAGE = [&](int p, int kc) {
        const uint32_t sb = sbase + p * STAGE_B;
        #pragma unroll
        for (int tile = 0; tile < 4; tile++) {
            const bf16* base = (tile == 0) ? tp0 : (tile == 1) ? tp1 : (tile == 2) ? tp2 : tp3;
            #pragma unroll
            for (int j = 0; j < 4; j++) {
                int c = tid + 256 * j;         // 0..1023
                int r = c >> 3, ch = c & 7;    // row, 16B chunk (8 per 128B row)
                CP_ASYNC16(sb + tile * TILE_B + r * ROWB + ch * 16,
                           base + (size_t)r * K + kc + ch * 8);
            }
        }
        CP_COMMIT();
    };

    STAGE(0, 0);
    STAGE(1, KC);

    // lane address components
    const int a_r  = wm * 64 + (lane & 15);
    const int a_c  = ((lane >> 4) & 1) * 16;
    const int b4_r = wn * 32 + (lane & 7) + ((lane >> 4) & 1) * 8;  // paired-x4 B
    const int b4_c = ((lane >> 3) & 1) * 16;

    for (int t = 0; t < T; t++) {
        const int p = t % 3;
        if (t + 1 < T) { CP_WAIT1(); } else { CP_WAIT0(); }
        __syncthreads();
        if (t + 2 < T) STAGE((t + 2) % 3, (t + 2) * KC);

        const uint32_t Ahb = sbase + p * STAGE_B;
        const uint32_t Alb = Ahb + TILE_B;
        const uint32_t Bhb = Alb + TILE_B;
        const uint32_t Blb = Bhb + TILE_B;

        #pragma unroll
        for (int ks = 0; ks < 4; ks++) {
            uint32_t ah[4][4], al[4][4], bh[4][2], bl[4][2];
            #pragma unroll
            for (int mt = 0; mt < 4; mt++) {
                uint32_t ro = (a_r + mt * 16) * ROWB + ks * 32 + a_c;
                ldsm_x4(ah[mt], Ahb + ro);
                ldsm_x4(al[mt], Alb + ro);
            }
            #pragma unroll
            for (int pr = 0; pr < 2; pr++) {
                uint32_t ro = (b4_r + pr * 16) * ROWB + ks * 32 + b4_c;
                ldsm_x4(&bh[2 * pr][0], Bhb + ro);   // fills bh[2pr], bh[2pr+1]
                ldsm_x4(&bl[2 * pr][0], Blb + ro);
            }
            #pragma unroll
            for (int mt = 0; mt < 4; mt++)
                #pragma unroll
                for (int nt = 0; nt < 4; nt++) {
                    mma_bf16(acc[mt][nt], ah[mt], bh[nt]);
                    mma_bf16(acc[mt][nt], ah[mt], bl[nt]);
                    mma_bf16(acc[mt][nt], al[mt], bh[nt]);
                }
        }
    }

    // ---- epilogue ----
    const int g  = lane >> 2;
    const int tg = lane & 3;
    #pragma unroll
    for (int mt = 0; mt < 4; mt++) {
        #pragma unroll
        for (int nt = 0; nt < 4; nt++) {
            int row = m0 + wm * 64 + mt * 16 + g;
            int col = n0 + wn * 32 + nt * 8 + 2 * tg;
            #pragma unroll
            for (int hh = 0; hh < 2; hh++) {
                int r = row + hh * 8;
                float2 v;
                v.x = acc[mt][nt][2 * hh + 0];
                v.y = acc[mt][nt][2 * hh + 1];
                if (EPI == 1 || EPI == 2) { v.x += bias[col]; v.y += bias[col + 1]; }
                if (EPI == 1) {
                    v.x = fmaxf(v.x, 0.f); v.y = fmaxf(v.y, 0.f);
                    bf16 h0, l0, h1, l1;
                    splitbf(v.x, h0, l0); splitbf(v.y, h1, l1);
                    bf16 hp[2] = {h0, h1}, lp[2] = {l0, l1};
                    *(uint32_t*)(CH + (size_t)r * ldc + col) = *(uint32_t*)hp;
                    *(uint32_t*)(CL + (size_t)r * ldc + col) = *(uint32_t*)lp;
                } else if (EPI == 3) {
                    int sec = col >> 10;
                    int hd  = (col >> 6) & 15;
                    int d   = col & 63;
                    int bb  = r >> 10, s = r & 1023;
                    size_t o = ((size_t)(bb * HEADS + hd) * SEQ + s) * HDIM + d;
                    float sc = (sec == 0) ? 8.f : 1.f;
                    v.x *= sc; v.y *= sc;
                    bf16 h0, l0, h1, l1;
                    splitbf(v.x, h0, l0); splitbf(v.y, h1, l1);
                    bf16 hp[2] = {h0, h1}, lp[2] = {l0, l1};
                    bf16* H = (sec == 0) ? oQH : (sec == 1) ? oKH : oVH;
                    bf16* L = (sec == 0) ? oQL : (sec == 1) ? oKL : oVL;
                    *(uint32_t*)(H + o) = *(uint32_t*)hp;
                    *(uint32_t*)(L + o) = *(uint32_t*)lp;
                } else {
                    if (EPI == 2) {
                        const float2 rr = *(const float2*)(res + (size_t)r * ldc + col);
                        v.x += rr.x; v.y += rr.y;
                    }
                    *(float2*)(C + (size_t)r * ldc + col) = v;
                }
            }
        }
    }
}

// ================= tensor-core flash attention (3xBF16) =================
#define FT_ROWB 144
#define FT_TILE (64 * FT_ROWB)
#define FT_SMEM (2 * FT_TILE + 8 * FT_TILE)

__global__ void __launch_bounds__(128, 2)
flash_attn_tc_kernel(const bf16* __restrict__ QH, const bf16* __restrict__ QL,
                     const bf16* __restrict__ KH, const bf16* __restrict__ KL,
                     const bf16* __restrict__ VH, const bf16* __restrict__ VL,
                     float* __restrict__ O)
{
    extern __shared__ char smc[];
    const uint32_t sb = smem_u32(smc);
    const int tid = threadIdx.x, wid = tid >> 5, lane = tid & 31;
    const int g = lane >> 2, tg = lane & 3;
    const int q0 = blockIdx.x * 64;
    const int bh = blockIdx.z * HEADS + blockIdx.y;
    const size_t hb = (size_t)bh * SEQ * HDIM;

    const uint32_t sQH = sb, sQL = sb + FT_TILE;

    auto STAGE_KV = [&](int p, int kt) {
        uint32_t st = sb + 2 * FT_TILE + p * 4 * FT_TILE;
        const bf16* bases[4] = {KH + hb, KL + hb, VH + hb, VL + hb};
        #pragma unroll
        for (int tile = 0; tile < 4; tile++) {
            #pragma unroll
            for (int j = 0; j < 4; j++) {
                int c = tid + 128 * j;
                int r = c >> 3, ch = c & 7;
                CP_ASYNC16(st + tile * FT_TILE + r * FT_ROWB + ch * 16,
                           bases[tile] + (size_t)(kt * 64 + r) * HDIM + ch * 8);
            }
        }
        CP_COMMIT();
    };

    {
        const bf16* qb[2] = {QH + hb, QL + hb};
        #pragma unroll
        for (int tile = 0; tile < 2; tile++)
            #pragma unroll
            for (int j = 0; j < 4; j++) {
                int c = tid + 128 * j;
                int r = c >> 3, ch = c & 7;
                CP_ASYNC16((tile ? sQL : sQH) + r * FT_ROWB + ch * 16,
                           qb[tile] + (size_t)(q0 + r) * HDIM + ch * 8);
            }
        uint32_t st = sb + 2 * FT_TILE;
        const bf16* bases[4] = {KH + hb, KL + hb, VH + hb, VL + hb};
        #pragma unroll
        for (int tile = 0; tile < 4; tile++)
            #pragma unroll
            for (int j = 0; j < 4; j++) {
                int c = tid + 128 * j;
                int r = c >> 3, ch = c & 7;
                CP_ASYNC16(st + tile * FT_TILE + r * FT_ROWB + ch * 16,
                           bases[tile] + (size_t)r * HDIM + ch * 8);
            }
        CP_COMMIT();
    }
    STAGE_KV(1, 1);

    CP_WAIT1();
    __syncthreads();

    uint32_t qh[4][4], ql[4][4];
    const int a_r = wid * 16 + (lane & 15);
    const int a_c = ((lane >> 4) & 1) * 16;
    #pragma unroll
    for (int ks = 0; ks < 4; ks++) {
        ldsm_x4(qh[ks], sQH + a_r * FT_ROWB + ks * 32 + a_c);
        ldsm_x4(ql[ks], sQL + a_r * FT_ROWB + ks * 32 + a_c);
    }

    float acco[8][4];
    #pragma unroll
    for (int nt = 0; nt < 8; nt++)
        #pragma unroll
        for (int q = 0; q < 4; q++) acco[nt][q] = 0.f;
    float mrow[2] = {-1e30f, -1e30f};
    float lrow[2] = {0.f, 0.f};

    const int b_r = lane & 7;
    const int b_c = ((lane >> 3) & 1) * 16;
    const int v_r = (lane & 7) + ((lane >> 3) & 1) * 8;

    const int T = SEQ / 64;
    for (int t = 0; t < T; t++) {
        if (t > 0) {
            if (t + 1 < T) { CP_WAIT1(); } else { CP_WAIT0(); }
            __syncthreads();
        }
        const uint32_t st  = sb + 2 * FT_TILE + (t & 1) * 4 * FT_TILE;
        const uint32_t sKH = st, sKL = st + FT_TILE;
        const uint32_t sVH = st + 2 * FT_TILE, sVL = st + 3 * FT_TILE;

        float accs[8][4];
        #pragma unroll
        for (int nt = 0; nt < 8; nt++)
            #pragma unroll
            for (int q = 0; q < 4; q++) accs[nt][q] = 0.f;

        #pragma unroll
        for (int ks = 0; ks < 4; ks++) {
            #pragma unroll
            for (int nt = 0; nt < 8; nt++) {
                uint32_t kh2[2], kl2[2];
                uint32_t ro = (nt * 8 + b_r) * FT_ROWB + ks * 32 + b_c;
                ldsm_x2(kh2, sKH + ro);
                ldsm_x2(kl2, sKL + ro);
                mma_bf16(accs[nt], qh[ks], kh2);
                mma_bf16(accs[nt], qh[ks], kl2);
                mma_bf16(accs[nt], ql[ks], kh2);
            }
        }

        #pragma unroll
        for (int h = 0; h < 2; h++) {
            float mx = accs[0][2 * h];
            #pragma unroll
            for (int nt = 0; nt < 8; nt++)
                mx = fmaxf(mx, fmaxf(accs[nt][2 * h], accs[nt][2 * h + 1]));
            mx = fmaxf(mx, __shfl_xor_sync(0xffffffffu, mx, 1));
            mx = fmaxf(mx, __shfl_xor_sync(0xffffffffu, mx, 2));
            float mn = fmaxf(mrow[h], mx);
            float corr = __expf(mrow[h] - mn);
            float sum = 0.f;
            #pragma unroll
            for (int nt = 0; nt < 8; nt++) {
                float e0 = __expf(accs[nt][2 * h] - mn);
                float e1 = __expf(accs[nt][2 * h + 1] - mn);
                accs[nt][2 * h] = e0; accs[nt][2 * h + 1] = e1;
                sum += e0 + e1;
            }
            sum += __shfl_xor_sync(0xffffffffu, sum, 1);
            sum += __shfl_xor_sync(0xffffffffu, sum, 2);
            lrow[h] = lrow[h] * corr + sum;
            mrow[h] = mn;
            #pragma unroll
            for (int nt = 0; nt < 8; nt++) {
                acco[nt][2 * h] *= corr; acco[nt][2 * h + 1] *= corr;
            }
        }

        #pragma unroll
        for (int ks = 0; ks < 4; ks++) {
            uint32_t ph[4], pl[4];
            packsplit(accs[2 * ks][0],     accs[2 * ks][1],     ph[0], pl[0]);
            packsplit(accs[2 * ks][2],     accs[2 * ks][3],     ph[1], pl[1]);
            packsplit(accs[2 * ks + 1][0], accs[2 * ks + 1][1], ph[2], pl[2]);
            packsplit(accs[2 * ks + 1][2], accs[2 * ks + 1][3], ph[3], pl[3]);
            #pragma unroll
            for (int nt = 0; nt < 8; nt++) {
                uint32_t vh2[2], vl2[2];
                uint32_t ro = (ks * 16 + v_r) * FT_ROWB + nt * 16;
                ldsm_x2_t(vh2, sVH + ro);
                ldsm_x2_t(vl2, sVL + ro);
                mma_bf16(acco[nt], ph, vh2);
                mma_bf16(acco[nt], ph, vl2);
                mma_bf16(acco[nt], pl, vh2);
            }
        }

        __syncthreads();
        if (t + 2 < T) STAGE_KV(t & 1, t + 2);
    }

    #pragma unroll
    for (int h = 0; h < 2; h++) {
        float inv = 1.f / lrow[h];
        int s = q0 + wid * 16 + g + h * 8;
        float* orow = O + ((size_t)(blockIdx.z * SEQ + s)) * D_MODEL + blockIdx.y * HDIM;
        #pragma unroll
        for (int nt = 0; nt < 8; nt++) {
            float2 v;
            v.x = acco[nt][2 * h] * inv;
            v.y = acco[nt][2 * h + 1] * inv;
            *(float2*)(orow + nt * 8 + 2 * tg) = v;
        }
    }
}

// ================= layernorm =================
__global__ __launch_bounds__(256) void ln_kernel(const float* __restrict__ A,
                                                 const float* __restrict__ Add,
                                                 const float* __restrict__ g,
                                                 const float* __restrict__ bb,
                                                 float* __restrict__ out,
                                                 bf16* __restrict__ outH,
                                                 bf16* __restrict__ outL,
                                                 int useAdd)
{
    __shared__ float red[8];
    const int row = blockIdx.x;
    const size_t off = (size_t)row * D_MODEL;
    const int tid = threadIdx.x;

    float x[4]; float s = 0.f;
    #pragma unroll
    for (int i = 0; i < 4; i++) {
        int c = tid + 256 * i;
        float v = A[off + c];
        if (useAdd) v += Add[off + c];
        x[i] = v; s += v;
    }
    #pragma unroll
    for (int o = 16; o > 0; o >>= 1) s += __shfl_xor_sync(0xffffffffu, s, o);
    if ((tid & 31) == 0) red[tid >> 5] = s;
    __syncthreads();
    float tot = 0.f;
    #pragma unroll
    for (int i = 0; i < 8; i++) tot += red[i];
    const float mean = tot * (1.0f / 1024.0f);

    float vs = 0.f;
    #pragma unroll
    for (int i = 0; i < 4; i++) { float d = x[i] - mean; vs += d * d; }
    #pragma unroll
    for (int o = 16; o > 0; o >>= 1) vs += __shfl_xor_sync(0xffffffffu, vs, o);
    __syncthreads();
    if ((tid & 31) == 0) red[tid >> 5] = vs;
    __syncthreads();
    float vt = 0.f;
    #pragma unroll
    for (int i = 0; i < 8; i++) vt += red[i];
    const float inv = rsqrtf(vt * (1.0f / 1024.0f) + 1e-5f);

    #pragma unroll
    for (int i = 0; i < 4; i++) {
        int c = tid + 256 * i;
        float v = (x[i] - mean) * inv * g[c] + bb[c];
        out[off + c] = v;
        if (outH) {
            bf16 h, l; splitbf(v, h, l);
            outH[off + c] = h; outL[off + c] = l;
        }
    }
}

// ================= launch =================
extern "C" void kernel_launch(void* const* d_in, const int* in_sizes, int n_in,
                              void* d_out, int out_size)
{
    const float* input = (const float*)d_in[0];
    const float* pos   = (const float*)d_in[1];
    const float* Wq    = (const float*)d_in[2];
    const float* Wk    = (const float*)d_in[3];
    const float* Wv    = (const float*)d_in[4];
    const float* W1    = (const float*)d_in[5];
    const float* b1    = (const float*)d_in[6];
    const float* W2    = (const float*)d_in[7];
    const float* b2    = (const float*)d_in[8];
    const float* ln1g  = (const float*)d_in[9];
    const float* ln1b  = (const float*)d_in[10];
    const float* ln2g  = (const float*)d_in[11];
    const float* ln2b  = (const float*)d_in[12];
    float* out = (float*)d_out;

    float *attn, *x1, *h;
    bf16 *qkinH, *qkinL, *inH, *inL, *x1H, *x1L, *ff1H, *ff1L;
    bf16 *QH, *QL, *KHp, *KLp, *VHp, *VLp;
    bf16 *WqkvTH, *WqkvTL, *W1TH, *W1TL, *W2TH, *W2TL;
    cudaGetSymbolAddress((void**)&attn,   g_attn);
    cudaGetSymbolAddress((void**)&x1,     g_x1);
    cudaGetSymbolAddress((void**)&h,      g_h);
    cudaGetSymbolAddress((void**)&qkinH,  g_qkinH);
    cudaGetSymbolAddress((void**)&qkinL,  g_qkinL);
    cudaGetSymbolAddress((void**)&inH,    g_inH);
    cudaGetSymbolAddress((void**)&inL,    g_inL);
    cudaGetSymbolAddress((void**)&x1H,    g_x1H);
    cudaGetSymbolAddress((void**)&x1L,    g_x1L);
    cudaGetSymbolAddress((void**)&ff1H,   g_ff1H);
    cudaGetSymbolAddress((void**)&ff1L,   g_ff1L);
    cudaGetSymbolAddress((void**)&QH,     g_QH);
    cudaGetSymbolAddress((void**)&QL,     g_QL);
    cudaGetSymbolAddress((void**)&KHp,    g_KH);
    cudaGetSymbolAddress((void**)&KLp,    g_KL);
    cudaGetSymbolAddress((void**)&VHp,    g_VH);
    cudaGetSymbolAddress((void**)&VLp,    g_VL);
    cudaGetSymbolAddress((void**)&WqkvTH, g_WqkvTH);
    cudaGetSymbolAddress((void**)&WqkvTL, g_WqkvTL);
    cudaGetSymbolAddress((void**)&W1TH,   g_W1TH);
    cudaGetSymbolAddress((void**)&W1TL,   g_W1TL);
    cudaGetSymbolAddress((void**)&W2TH,   g_W2TH);
    cudaGetSymbolAddress((void**)&W2TL,   g_W2TL);

    cudaFuncSetAttribute(flash_attn_tc_kernel,
                         cudaFuncAttributeMaxDynamicSharedMemorySize, FT_SMEM);
    cudaFuncSetAttribute(mma_gemm_kernel<3, true>,
                         cudaFuncAttributeMaxDynamicSharedMemorySize, MG_SMEM);
    cudaFuncSetAttribute(mma_gemm_kernel<1, false>,
                         cudaFuncAttributeMaxDynamicSharedMemorySize, MG_SMEM);
    cudaFuncSetAttribute(mma_gemm_kernel<2, false>,
                         cudaFuncAttributeMaxDynamicSharedMemorySize, MG_SMEM);

    // 0) weight transpose + split
    transpose_split_kernel<<<dim3(32, 32),  256>>>(Wq, WqkvTH,                   WqkvTL,                   1024, 1024);
    transpose_split_kernel<<<dim3(32, 32),  256>>>(Wk, WqkvTH + 1024 * 1024,     WqkvTL + 1024 * 1024,     1024, 1024);
    transpose_split_kernel<<<dim3(32, 32),  256>>>(Wv, WqkvTH + 2 * 1024 * 1024, WqkvTL + 2 * 1024 * 1024, 1024, 1024);
    transpose_split_kernel<<<dim3(128, 32), 256>>>(W1, W1TH, W1TL, 1024, 4096);
    transpose_split_kernel<<<dim3(32, 128), 256>>>(W2, W2TH, W2TL, 4096, 1024);

    // 1) activation splits (merged)
    {
        int n4 = ROWS * D_MODEL / 4;
        split2_kernel<<<(n4 + 255) / 256, 256>>>(input, pos, qkinH, qkinL, inH, inL, n4);
    }

    // 2) fused QKV projection -> per-head split bf16 (Q pre-scaled by 8)
    mma_gemm_kernel<3, true><<<dim3(24, 32), 256, MG_SMEM>>>(
        qkinH, qkinL, inH, inL, WqkvTH, WqkvTL,
        nullptr, nullptr, nullptr, nullptr, nullptr,
        QH, QL, KHp, KLp, VHp, VLp, 1024, 3 * D_MODEL);

    // 3) tensor-core attention
    flash_attn_tc_kernel<<<dim3(SEQ / 64, HEADS, BATCH), 128, FT_SMEM>>>(
        QH, QL, KHp, KLp, VHp, VLp, attn);

    // 4) x1 = LN(input + attn)
    ln_kernel<<<ROWS, 256>>>(input, attn, ln1g, ln1b, x1, x1H, x1L, 1);

    // 5) ff1 = relu(x1 @ W1 + b1) -> bf16 hi/lo
    mma_gemm_kernel<1, false><<<dim3(32, 32), 256, MG_SMEM>>>(
        x1H, x1L, nullptr, nullptr, W1TH, W1TL,
        b1, nullptr, nullptr, ff1H, ff1L,
        nullptr, nullptr, nullptr, nullptr, nullptr, nullptr, 1024, FF_DIM);

    // 6) h = ff1 @ W2 + b2 + x1
    mma_gemm_kernel<2, false><<<dim3(8, 32), 256, MG_SMEM>>>(
        ff1H, ff1L, nullptr, nullptr, W2TH, W2TL,
        b2, x1, h, nullptr, nullptr,
        nullptr, nullptr, nullptr, nullptr, nullptr, nullptr, 4096, D_MODEL);

    // 7) out = LN(h)
    ln_kernel<<<ROWS, 256>>>(h, h, ln2g, ln2b, out, nullptr, nullptr, 0);
}